// round 1
// baseline (speedup 1.0000x reference)
#include <cuda_runtime.h>
#include <cuda_bf16.h>
#include <math.h>

// Problem constants
#define NN   10000
#define EE   80000
#define SD   18
#define HID  1024
#define LAYERS 4

// ---------------------------------------------------------------------------
// Scratch (device globals — no runtime allocation allowed)
// ---------------------------------------------------------------------------
__device__ float g_h [NN * HID];
__device__ float g_HA[NN * HID];
__device__ float g_HB[NN * HID];
__device__ float g_R [NN * HID];
__device__ float g_A [LAYERS * HID * HID];   // W1a - W1b per layer
__device__ float g_t [NN * 256];             // ghost head intermediate
__device__ int   g_deg[NN];
__device__ int   g_off[NN + 1];
__device__ int   g_cur[NN];
__device__ int   g_srcs[EE];

// ---------------------------------------------------------------------------
// A = W1[:HID] - W1[HID:] per layer
// ---------------------------------------------------------------------------
__global__ void make_A_kernel(const float* __restrict__ W1, float* __restrict__ Aout) {
    int idx = blockIdx.x * blockDim.x + threadIdx.x;
    if (idx >= LAYERS * HID * HID) return;
    int l  = idx >> 20;            // /(1024*1024)
    int rc = idx & ((1 << 20) - 1);
    Aout[idx] = W1[(size_t)l * 2 * HID * HID + rc]
              - W1[(size_t)l * 2 * HID * HID + HID * HID + rc];
}

// ---------------------------------------------------------------------------
// CSR build (deterministic: atomic scatter then per-node sort)
// ---------------------------------------------------------------------------
__global__ void zero_int_kernel(int* p, int n) {
    int i = blockIdx.x * blockDim.x + threadIdx.x;
    if (i < n) p[i] = 0;
}
__global__ void hist_kernel(const int* __restrict__ dst, int* __restrict__ deg) {
    int e = blockIdx.x * blockDim.x + threadIdx.x;
    if (e < EE) atomicAdd(&deg[dst[e]], 1);
}
__global__ void scan_kernel(const int* __restrict__ deg, int* __restrict__ off) {
    // single block of 1024 threads, serial chunks with carry
    __shared__ int sh[1024];
    __shared__ int carry;
    if (threadIdx.x == 0) { carry = 0; off[0] = 0; }
    __syncthreads();
    for (int start = 0; start < NN; start += 1024) {
        int i = start + threadIdx.x;
        int v = (i < NN) ? deg[i] : 0;
        sh[threadIdx.x] = v;
        __syncthreads();
        for (int d = 1; d < 1024; d <<= 1) {
            int t = (threadIdx.x >= d) ? sh[threadIdx.x - d] : 0;
            __syncthreads();
            sh[threadIdx.x] += t;
            __syncthreads();
        }
        if (i < NN) off[i + 1] = carry + sh[threadIdx.x];
        __syncthreads();
        if (threadIdx.x == 1023) carry += sh[1023];
        __syncthreads();
    }
}
__global__ void copy_off_kernel(const int* __restrict__ off, int* __restrict__ cur) {
    int i = blockIdx.x * blockDim.x + threadIdx.x;
    if (i < NN) cur[i] = off[i];
}
__global__ void scatter_kernel(const int* __restrict__ src, const int* __restrict__ dst,
                               int* __restrict__ cur, int* __restrict__ srcs) {
    int e = blockIdx.x * blockDim.x + threadIdx.x;
    if (e < EE) {
        int p = atomicAdd(&cur[dst[e]], 1);
        srcs[p] = src[e];
    }
}
__global__ void sort_kernel(const int* __restrict__ off, int* __restrict__ srcs) {
    int i = blockIdx.x * blockDim.x + threadIdx.x;
    if (i >= NN) return;
    int a = off[i], b = off[i + 1];
    for (int x = a + 1; x < b; x++) {
        int v = srcs[x];
        int y = x - 1;
        while (y >= a && srcs[y] > v) { srcs[y + 1] = srcs[y]; y--; }
        srcs[y + 1] = v;
    }
}

// ---------------------------------------------------------------------------
// Inverse phase embedding: h = sin(x@proj_w)*cos(x@proj_w)
// ---------------------------------------------------------------------------
__global__ void proj_kernel(const float* __restrict__ x, const float* __restrict__ pw,
                            float* __restrict__ h) {
    int idx = blockIdx.x * blockDim.x + threadIdx.x;
    if (idx >= NN * HID) return;
    int n = idx >> 10;
    int j = idx & (HID - 1);
    float p = 0.f;
#pragma unroll
    for (int k = 0; k < SD; k++) p = fmaf(x[n * SD + k], pw[k * HID + j], p);
    h[idx] = sinf(p) * cosf(p);
}

// ---------------------------------------------------------------------------
// SGEMM: C[M,N] = A[M,K] @ B[K,N], optional epilogues.
// MODE 0: plain   MODE 1: relu(acc + deg[row]*bias[col])   MODE 2: relu(acc + bias[col])
// BM=BN=128, BK=16, 256 threads, 8x8 per thread.
// ---------------------------------------------------------------------------
template <int MODE>
__global__ __launch_bounds__(256, 2)
void sgemm_kernel(const float* __restrict__ A, const float* __restrict__ B,
                  float* __restrict__ C, int M, int N, int K,
                  const float* __restrict__ bias, const int* __restrict__ deg) {
    __shared__ float As[16][132];
    __shared__ float Bs[16][128];

    const int tid  = threadIdx.x;
    const int bm   = blockIdx.y * 128;
    const int bn   = blockIdx.x * 128;
    const int tx   = tid & 15;
    const int ty   = tid >> 4;
    const int row0 = ty * 8;
    const int col0 = tx * 8;

    const int ar = tid >> 2;          // 0..63 (rows, +64 second pass)
    const int ac = (tid & 3) * 4;     // k offset within tile
    const int br = tid >> 5;          // 0..7  (k rows, +8 second pass)
    const int bc = (tid & 31) * 4;    // n offset within tile

    float acc[8][8];
#pragma unroll
    for (int i = 0; i < 8; i++)
#pragma unroll
        for (int j = 0; j < 8; j++) acc[i][j] = 0.f;

    for (int k0 = 0; k0 < K; k0 += 16) {
#pragma unroll
        for (int r = 0; r < 2; r++) {
            int row  = ar + r * 64;
            int grow = bm + row;
            float4 v = make_float4(0.f, 0.f, 0.f, 0.f);
            if (grow < M)
                v = *reinterpret_cast<const float4*>(&A[(size_t)grow * K + k0 + ac]);
            As[ac + 0][row] = v.x;
            As[ac + 1][row] = v.y;
            As[ac + 2][row] = v.z;
            As[ac + 3][row] = v.w;
        }
#pragma unroll
        for (int r = 0; r < 2; r++) {
            int row = br + r * 8;
            float4 v = *reinterpret_cast<const float4*>(&B[(size_t)(k0 + row) * N + bn + bc]);
            *reinterpret_cast<float4*>(&Bs[row][bc]) = v;
        }
        __syncthreads();
#pragma unroll
        for (int kk = 0; kk < 16; kk++) {
            float a[8], b[8];
#pragma unroll
            for (int i = 0; i < 8; i++) a[i] = As[kk][row0 + i];
#pragma unroll
            for (int j = 0; j < 8; j++) b[j] = Bs[kk][col0 + j];
#pragma unroll
            for (int i = 0; i < 8; i++)
#pragma unroll
                for (int j = 0; j < 8; j++) acc[i][j] = fmaf(a[i], b[j], acc[i][j]);
        }
        __syncthreads();
    }

#pragma unroll
    for (int i = 0; i < 8; i++) {
        int grow = bm + row0 + i;
        if (grow < M) {
            float degf = 0.f;
            if (MODE == 1) degf = (float)deg[grow];
#pragma unroll
            for (int j = 0; j < 8; j++) {
                int gcol = bn + col0 + j;
                float v  = acc[i][j];
                if (MODE == 1) v = fmaxf(fmaf(degf, bias[gcol], v), 0.f);
                if (MODE == 2) v = fmaxf(v + bias[gcol], 0.f);
                C[(size_t)grow * N + gcol] = v;
            }
        }
    }
}

// ---------------------------------------------------------------------------
// Edge aggregation: R[i] = sum_{e: dst=i} relu(HA[i] + HB[src_e] + b1)
// one block (256 threads) per node, 4 columns per thread
// ---------------------------------------------------------------------------
__global__ void edge_agg_kernel(const float* __restrict__ HA, const float* __restrict__ HB,
                                const int* __restrict__ off, const int* __restrict__ srcs,
                                const float* __restrict__ b1, float* __restrict__ R) {
    int i   = blockIdx.x;
    int tid = threadIdx.x;
    float ha[4], acc[4];
#pragma unroll
    for (int u = 0; u < 4; u++) {
        int j  = tid + u * 256;
        ha[u]  = HA[(size_t)i * HID + j] + b1[j];
        acc[u] = 0.f;
    }
    int s0 = off[i], s1 = off[i + 1];
    for (int e = s0; e < s1; e++) {
        int s = srcs[e];
        const float* hb = HB + (size_t)s * HID;
#pragma unroll
        for (int u = 0; u < 4; u++) {
            float v = ha[u] + hb[tid + u * 256];
            acc[u] += fmaxf(v, 0.f);
        }
    }
#pragma unroll
    for (int u = 0; u < 4; u++) R[(size_t)i * HID + tid + u * 256] = acc[u];
}

// ---------------------------------------------------------------------------
// Heads
// ---------------------------------------------------------------------------
__global__ void ghost_kernel(const float* __restrict__ t, const float* __restrict__ gw2,
                             const float* __restrict__ gb2, float* __restrict__ out) {
    int warp = (blockIdx.x * blockDim.x + threadIdx.x) >> 5;
    int lane = threadIdx.x & 31;
    if (warp >= NN) return;
    float s = 0.f;
#pragma unroll
    for (int k = lane; k < 256; k += 32) s = fmaf(t[(size_t)warp * 256 + k], gw2[k], s);
#pragma unroll
    for (int o = 16; o; o >>= 1) s += __shfl_xor_sync(0xFFFFFFFFu, s, o);
    if (lane == 0) out[warp] = 1.f / (1.f + expf(-(s + gb2[0])));
}

__global__ void stable_kernel(const float* __restrict__ h, const float* __restrict__ sw,
                              const float* __restrict__ sb, float* __restrict__ out) {
    int n    = blockIdx.x;
    int c    = threadIdx.y;
    int lane = threadIdx.x;
    float s  = 0.f;
    for (int k = lane; k < HID; k += 32) s = fmaf(h[(size_t)n * HID + k], sw[k * SD + c], s);
#pragma unroll
    for (int o = 16; o; o >>= 1) s += __shfl_xor_sync(0xFFFFFFFFu, s, o);
    if (lane == 0) out[(size_t)n * SD + c] = s + sb[c];
}

__global__ void copy_kernel(const float* __restrict__ src, float* __restrict__ dst, int n) {
    int i = blockIdx.x * blockDim.x + threadIdx.x;
    if (i < n) dst[i] = src[i];
}

// ---------------------------------------------------------------------------
// Launch
// ---------------------------------------------------------------------------
extern "C" void kernel_launch(void* const* d_in, const int* in_sizes, int n_in,
                              void* d_out, int out_size) {
    const float* x      = (const float*)d_in[0];
    const int*   eidx   = (const int*)  d_in[1];
    const float* proj_w = (const float*)d_in[2];
    const float* W1     = (const float*)d_in[3];
    const float* b1     = (const float*)d_in[4];
    const float* W2     = (const float*)d_in[5];
    const float* b2     = (const float*)d_in[6];
    const float* gw1    = (const float*)d_in[7];
    const float* gb1    = (const float*)d_in[8];
    const float* gw2    = (const float*)d_in[9];
    const float* gb2    = (const float*)d_in[10];
    const float* sw     = (const float*)d_in[11];
    const float* sb     = (const float*)d_in[12];
    float* out = (float*)d_out;

    const int* e_src = eidx;
    const int* e_dst = eidx + EE;

    float *p_h, *p_HA, *p_HB, *p_R, *p_A, *p_t;
    int *p_deg, *p_off, *p_cur, *p_srcs;
    cudaGetSymbolAddress((void**)&p_h,    g_h);
    cudaGetSymbolAddress((void**)&p_HA,   g_HA);
    cudaGetSymbolAddress((void**)&p_HB,   g_HB);
    cudaGetSymbolAddress((void**)&p_R,    g_R);
    cudaGetSymbolAddress((void**)&p_A,    g_A);
    cudaGetSymbolAddress((void**)&p_t,    g_t);
    cudaGetSymbolAddress((void**)&p_deg,  g_deg);
    cudaGetSymbolAddress((void**)&p_off,  g_off);
    cudaGetSymbolAddress((void**)&p_cur,  g_cur);
    cudaGetSymbolAddress((void**)&p_srcs, g_srcs);

    // 1) Precompute A = W1a - W1b for all layers
    {
        int tot = LAYERS * HID * HID;
        make_A_kernel<<<(tot + 255) / 256, 256>>>(W1, p_A);
    }

    // 2) CSR build
    zero_int_kernel<<<(NN + 255) / 256, 256>>>(p_deg, NN);
    hist_kernel<<<(EE + 255) / 256, 256>>>(e_dst, p_deg);
    scan_kernel<<<1, 1024>>>(p_deg, p_off);
    copy_off_kernel<<<(NN + 255) / 256, 256>>>(p_off, p_cur);
    scatter_kernel<<<(EE + 255) / 256, 256>>>(e_src, e_dst, p_cur, p_srcs);
    sort_kernel<<<(NN + 255) / 256, 256>>>(p_off, p_srcs);

    // 3) Phase embedding
    proj_kernel<<<(NN * HID + 255) / 256, 256>>>(x, proj_w, p_h);

    // 4) Layers
    dim3 g1024((HID + 127) / 128, (NN + 127) / 128);
    for (int l = 0; l < LAYERS; l++) {
        const float* Al  = p_A + (size_t)l * HID * HID;
        const float* Bl  = W1  + (size_t)l * 2 * HID * HID + (size_t)HID * HID;
        const float* W2l = W2  + (size_t)l * HID * HID;
        const float* b1l = b1  + (size_t)l * HID;
        const float* b2l = b2  + (size_t)l * HID;

        sgemm_kernel<0><<<g1024, 256>>>(p_h, Al, p_HA, NN, HID, HID, nullptr, nullptr);
        sgemm_kernel<0><<<g1024, 256>>>(p_h, Bl, p_HB, NN, HID, HID, nullptr, nullptr);
        edge_agg_kernel<<<NN, 256>>>(p_HA, p_HB, p_off, p_srcs, b1l, p_R);
        sgemm_kernel<1><<<g1024, 256>>>(p_R, W2l, p_h, NN, HID, HID, b2l, p_deg);
    }

    // 5) Heads
    dim3 g256((256 + 127) / 128, (NN + 127) / 128);
    sgemm_kernel<2><<<g256, 256>>>(p_h, gw1, p_t, NN, 256, HID, gb1, nullptr);
    ghost_kernel<<<(NN * 32 + 255) / 256, 256>>>(p_t, gw2, gb2, out);
    stable_kernel<<<NN, dim3(32, SD)>>>(p_h, sw, sb, out + NN);
    copy_kernel<<<(NN * HID + 255) / 256, 256>>>(p_h, out + NN + NN * SD, NN * HID);
}

// round 3
// speedup vs baseline: 2.1754x; 2.1754x over previous
#include <cuda_runtime.h>
#include <cuda_bf16.h>
#include <math.h>
#include <stdint.h>

// Problem constants
#define NN   10000
#define EE   80000
#define SD   18
#define HID  1024
#define K3   3072          // split-K: [hi | lo | hi] x [whi | whi | wlo]
#define LAYERS 4

// GEMM tiling
#define BM 128
#define BN 128
#define BK 32
#define STG 4
#define NK (K3 / BK)               // 96
#define PADB 80                    // padded smem row stride in bytes (40 bf16)
#define TILE_BYTES (128 * PADB)    // 10240
#define STAGE_BYTES (2 * TILE_BYTES)
#define MM_SMEM (STG * STAGE_BYTES)   // 81920

// ---------------------------------------------------------------------------
// Scratch (device globals — no runtime allocation allowed)
// ---------------------------------------------------------------------------
__device__ float g_h  [NN * HID];
__device__ float g_HAB[NN * 2048];
__device__ float g_t  [NN * 256];
__device__ __nv_bfloat16 g_Abig[NN * K3];
__device__ __nv_bfloat16 g_Rbig[NN * K3];
__device__ __nv_bfloat16 g_WtAB[LAYERS * 2048 * K3];
__device__ __nv_bfloat16 g_WtW2[LAYERS * HID * K3];
__device__ __nv_bfloat16 g_WtG [256 * K3];
__device__ int   g_deg[NN];
__device__ int   g_off[NN + 1];
__device__ int   g_cur[NN];
__device__ int   g_srcs[EE];

// ---------------------------------------------------------------------------
// PTX helpers (baseline ISA only: cp.async / ldmatrix / mma.sync)
// ---------------------------------------------------------------------------
__device__ __forceinline__ uint32_t smem_u32(const void* p) {
    uint32_t a;
    asm("{ .reg .u64 t; cvta.to.shared.u64 t, %1; cvt.u32.u64 %0, t; }" : "=r"(a) : "l"(p));
    return a;
}
__device__ __forceinline__ void cp16(uint32_t dst, const void* src, bool valid) {
    int sz = valid ? 16 : 0;
    asm volatile("cp.async.cg.shared.global [%0], [%1], 16, %2;" :: "r"(dst), "l"(src), "r"(sz) : "memory");
}
__device__ __forceinline__ void cp_commit() { asm volatile("cp.async.commit_group;" ::: "memory"); }
__device__ __forceinline__ void ldm_x4(uint32_t& r0, uint32_t& r1, uint32_t& r2, uint32_t& r3,
                                       uint32_t addr) {
    asm volatile("ldmatrix.sync.aligned.m8n8.x4.shared.b16 {%0,%1,%2,%3}, [%4];"
                 : "=r"(r0), "=r"(r1), "=r"(r2), "=r"(r3) : "r"(addr));
}
__device__ __forceinline__ void mma_bf16(float& c0, float& c1, float& c2, float& c3,
                                         uint32_t a0, uint32_t a1, uint32_t a2, uint32_t a3,
                                         uint32_t b0, uint32_t b1) {
    asm volatile(
        "mma.sync.aligned.m16n8k16.row.col.f32.bf16.bf16.f32 "
        "{%0,%1,%2,%3}, {%4,%5,%6,%7}, {%8,%9}, {%0,%1,%2,%3};"
        : "+f"(c0), "+f"(c1), "+f"(c2), "+f"(c3)
        : "r"(a0), "r"(a1), "r"(a2), "r"(a3), "r"(b0), "r"(b1));
}

// ---------------------------------------------------------------------------
// HMMA GEMM: C[M, Nstride] = A[M, K3] @ Bt[N, K3]^T  (bf16 in, fp32 out)
// MODE 0: plain
// MODE 1: v = relu(acc + deg[row]*bias[col]); writes C (fp32) AND abig split
// MODE 2: relu(acc + bias[col])
// 256 threads, warp grid 4(M) x 2(N); warp tile 32x64; frag m16n8k16.
// ---------------------------------------------------------------------------
template <int MODE>
__global__ void __launch_bounds__(256)
mma_gemm(const __nv_bfloat16* __restrict__ A, const __nv_bfloat16* __restrict__ Bt,
         float* __restrict__ C, int M, int Nstride,
         const float* __restrict__ bias, const int* __restrict__ deg,
         __nv_bfloat16* __restrict__ abig) {
    extern __shared__ char smem[];
    const uint32_t sb = smem_u32(smem);
    const int tid  = threadIdx.x;
    const int wid  = tid >> 5;
    const int lane = tid & 31;
    const int bm   = blockIdx.y * BM;
    const int bn   = blockIdx.x * BN;
    const int warp_m = (wid & 3) * 32;
    const int warp_n = (wid >> 2) * 64;

    // cp.async mapping: chunk c in [0,512): row=c>>2, col16=c&3. Threads own c=tid, tid+256.
    const int r0c = tid >> 2, c0c = tid & 3;
    const int r1c = (tid + 256) >> 2, c1c = tid & 3;
    const bool a0v = (bm + r0c) < M;
    const bool a1v = (bm + r1c) < M;
    const char* gA = (const char*)A  + (size_t)bm * (K3 * 2);
    const char* gB = (const char*)Bt + (size_t)bn * (K3 * 2);

    auto load_chunk = [&](int kc, int s) {
        uint32_t sa = sb + s * STAGE_BYTES;
        uint32_t sB = sa + TILE_BYTES;
        size_t kb = (size_t)kc * (BK * 2);
        cp16(sa + r0c * PADB + c0c * 16, gA + (size_t)r0c * (K3 * 2) + kb + c0c * 16, a0v);
        cp16(sa + r1c * PADB + c1c * 16, gA + (size_t)r1c * (K3 * 2) + kb + c1c * 16, a1v);
        cp16(sB + r0c * PADB + c0c * 16, gB + (size_t)r0c * (K3 * 2) + kb + c0c * 16, true);
        cp16(sB + r1c * PADB + c1c * 16, gB + (size_t)r1c * (K3 * 2) + kb + c1c * 16, true);
        cp_commit();
    };

    // ldmatrix lane-offset patterns
    const int g  = lane >> 3;
    const int lr = lane & 7;
    const int A_lane = ((g & 1) * 8 + lr) * PADB + (g >> 1) * 16;   // bytes
    const int B_lane = ((g >> 1) * 8 + lr) * PADB + (g & 1) * 16;   // bytes

    float acc[2][8][4];
#pragma unroll
    for (int i = 0; i < 2; i++)
#pragma unroll
        for (int j = 0; j < 8; j++)
#pragma unroll
            for (int q = 0; q < 4; q++) acc[i][j][q] = 0.f;

    // prologue
#pragma unroll
    for (int s = 0; s < STG - 1; s++) load_chunk(s, s);

    for (int it = 0; it < NK; it++) {
        asm volatile("cp.async.wait_group %0;" :: "n"(STG - 2) : "memory");
        __syncthreads();
        int cl = it + STG - 1;
        if (cl < NK) load_chunk(cl, cl % STG);
        else         cp_commit();      // empty group keeps wait_group bookkeeping valid

        uint32_t sa = sb + (it % STG) * STAGE_BYTES;
        uint32_t sB = sa + TILE_BYTES;
#pragma unroll
        for (int kk = 0; kk < 2; kk++) {
            uint32_t a[2][4], b[4][4];
#pragma unroll
            for (int mt = 0; mt < 2; mt++)
                ldm_x4(a[mt][0], a[mt][1], a[mt][2], a[mt][3],
                       sa + (warp_m + mt * 16) * PADB + kk * 32 + A_lane);
#pragma unroll
            for (int nt2 = 0; nt2 < 4; nt2++)
                ldm_x4(b[nt2][0], b[nt2][1], b[nt2][2], b[nt2][3],
                       sB + (warp_n + nt2 * 16) * PADB + kk * 32 + B_lane);
#pragma unroll
            for (int mt = 0; mt < 2; mt++)
#pragma unroll
                for (int nt = 0; nt < 8; nt++) {
                    uint32_t bb0 = b[nt >> 1][(nt & 1) * 2 + 0];
                    uint32_t bb1 = b[nt >> 1][(nt & 1) * 2 + 1];
                    mma_bf16(acc[mt][nt][0], acc[mt][nt][1], acc[mt][nt][2], acc[mt][nt][3],
                             a[mt][0], a[mt][1], a[mt][2], a[mt][3], bb0, bb1);
                }
        }
        __syncthreads();
    }

    // epilogue
    const int tq = lane >> 2;      // 0..7
    const int tr = lane & 3;       // 0..3
#pragma unroll
    for (int mt = 0; mt < 2; mt++) {
#pragma unroll
        for (int half = 0; half < 2; half++) {
            int row = bm + warp_m + mt * 16 + half * 8 + tq;
            if (row >= M) continue;
            float degf = 0.f;
            if (MODE == 1) degf = (float)deg[row];
#pragma unroll
            for (int nt = 0; nt < 8; nt++) {
                int col = bn + warp_n + nt * 8 + tr * 2;
                float vx = acc[mt][nt][half * 2 + 0];
                float vy = acc[mt][nt][half * 2 + 1];
                if (MODE == 1) {
                    vx = fmaxf(fmaf(degf, bias[col + 0], vx), 0.f);
                    vy = fmaxf(fmaf(degf, bias[col + 1], vy), 0.f);
                } else if (MODE == 2) {
                    vx = fmaxf(vx + bias[col + 0], 0.f);
                    vy = fmaxf(vy + bias[col + 1], 0.f);
                }
                *reinterpret_cast<float2*>(&C[(size_t)row * Nstride + col]) = make_float2(vx, vy);
                if (MODE == 1) {
                    __nv_bfloat162 hi2, lo2;
                    hi2.x = __float2bfloat16(vx);
                    hi2.y = __float2bfloat16(vy);
                    lo2.x = __float2bfloat16(vx - __bfloat162float(hi2.x));
                    lo2.y = __float2bfloat16(vy - __bfloat162float(hi2.y));
                    size_t base = (size_t)row * K3 + col;
                    *reinterpret_cast<__nv_bfloat162*>(&abig[base])            = hi2;
                    *reinterpret_cast<__nv_bfloat162*>(&abig[base + HID])      = lo2;
                    *reinterpret_cast<__nv_bfloat162*>(&abig[base + 2 * HID])  = hi2;
                }
            }
        }
    }
}

// ---------------------------------------------------------------------------
// Weight transpose + bf16 split: out[n][0:K]=hi, [K:2K]=hi, [2K:3K]=lo
// W is [K=1024, N] row-major (optionally Wa - Wb)
// ---------------------------------------------------------------------------
__global__ void convW_kernel(const float* __restrict__ Wa, const float* __restrict__ Wb,
                             __nv_bfloat16* __restrict__ out, int N) {
    __shared__ float t[32][33];
    int n0 = blockIdx.x * 32, k0 = blockIdx.y * 32;
    int tx = threadIdx.x, ty = threadIdx.y;
#pragma unroll
    for (int r = ty; r < 32; r += 8) {
        float v = Wa[(size_t)(k0 + r) * N + n0 + tx];
        if (Wb) v -= Wb[(size_t)(k0 + r) * N + n0 + tx];
        t[r][tx] = v;
    }
    __syncthreads();
#pragma unroll
    for (int r = ty; r < 32; r += 8) {
        int n = n0 + r, k = k0 + tx;
        float v = t[tx][r];
        __nv_bfloat16 hi = __float2bfloat16(v);
        __nv_bfloat16 lo = __float2bfloat16(v - __bfloat162float(hi));
        size_t base = (size_t)n * K3;
        out[base + k] = hi;
        out[base + HID + k] = hi;
        out[base + 2 * HID + k] = lo;
    }
}

// ---------------------------------------------------------------------------
// CSR build (deterministic)
// ---------------------------------------------------------------------------
__global__ void zero_int_kernel(int* p, int n) {
    int i = blockIdx.x * blockDim.x + threadIdx.x;
    if (i < n) p[i] = 0;
}
__global__ void hist_kernel(const int* __restrict__ dst, int* __restrict__ deg) {
    int e = blockIdx.x * blockDim.x + threadIdx.x;
    if (e < EE) atomicAdd(&deg[dst[e]], 1);
}
__global__ void scan_kernel(const int* __restrict__ deg, int* __restrict__ off) {
    __shared__ int sh[1024];
    __shared__ int carry;
    if (threadIdx.x == 0) { carry = 0; off[0] = 0; }
    __syncthreads();
    for (int start = 0; start < NN; start += 1024) {
        int i = start + threadIdx.x;
        int v = (i < NN) ? deg[i] : 0;
        sh[threadIdx.x] = v;
        __syncthreads();
        for (int d = 1; d < 1024; d <<= 1) {
            int t = (threadIdx.x >= d) ? sh[threadIdx.x - d] : 0;
            __syncthreads();
            sh[threadIdx.x] += t;
            __syncthreads();
        }
        if (i < NN) off[i + 1] = carry + sh[threadIdx.x];
        __syncthreads();
        if (threadIdx.x == 1023) carry += sh[1023];
        __syncthreads();
    }
}
__global__ void copy_off_kernel(const int* __restrict__ off, int* __restrict__ cur) {
    int i = blockIdx.x * blockDim.x + threadIdx.x;
    if (i < NN) cur[i] = off[i];
}
__global__ void scatter_kernel(const int* __restrict__ src, const int* __restrict__ dst,
                               int* __restrict__ cur, int* __restrict__ srcs) {
    int e = blockIdx.x * blockDim.x + threadIdx.x;
    if (e < EE) {
        int p = atomicAdd(&cur[dst[e]], 1);
        srcs[p] = src[e];
    }
}
__global__ void sort_kernel(const int* __restrict__ off, int* __restrict__ srcs) {
    int i = blockIdx.x * blockDim.x + threadIdx.x;
    if (i >= NN) return;
    int a = off[i], b = off[i + 1];
    for (int x = a + 1; x < b; x++) {
        int v = srcs[x];
        int y = x - 1;
        while (y >= a && srcs[y] > v) { srcs[y + 1] = srcs[y]; y--; }
        srcs[y + 1] = v;
    }
}

// ---------------------------------------------------------------------------
// Phase embedding: writes split-bf16 Abig directly
// ---------------------------------------------------------------------------
__global__ void proj_kernel(const float* __restrict__ x, const float* __restrict__ pw,
                            __nv_bfloat16* __restrict__ Abig) {
    int idx = blockIdx.x * blockDim.x + threadIdx.x;
    if (idx >= NN * HID) return;
    int n = idx >> 10, j = idx & (HID - 1);
    float p = 0.f;
#pragma unroll
    for (int k = 0; k < SD; k++) p = fmaf(x[n * SD + k], pw[k * HID + j], p);
    float v = sinf(p) * cosf(p);
    __nv_bfloat16 hi = __float2bfloat16(v);
    __nv_bfloat16 lo = __float2bfloat16(v - __bfloat162float(hi));
    size_t base = (size_t)n * K3;
    Abig[base + j] = hi;
    Abig[base + HID + j] = lo;
    Abig[base + 2 * HID + j] = hi;
}

// ---------------------------------------------------------------------------
// Edge aggregation: R[i] = sum relu(HA[i] + HB[src] + b1); writes split bf16
// HAB layout: row n holds [HA(n) | HB(n)] (2048 floats)
// ---------------------------------------------------------------------------
__global__ void edge_agg_kernel(const float* __restrict__ HAB,
                                const int* __restrict__ off, const int* __restrict__ srcs,
                                const float* __restrict__ b1, __nv_bfloat16* __restrict__ Rbig) {
    int i   = blockIdx.x;
    int tid = threadIdx.x;
    float ha[4], acc[4];
#pragma unroll
    for (int u = 0; u < 4; u++) {
        int j  = tid + u * 256;
        ha[u]  = HAB[(size_t)i * 2048 + j] + b1[j];
        acc[u] = 0.f;
    }
    int s0 = off[i], s1 = off[i + 1];
    for (int e = s0; e < s1; e++) {
        int s = srcs[e];
        const float* hb = HAB + (size_t)s * 2048 + 1024;
#pragma unroll
        for (int u = 0; u < 4; u++) acc[u] += fmaxf(ha[u] + hb[tid + u * 256], 0.f);
    }
    size_t base = (size_t)i * K3;
#pragma unroll
    for (int u = 0; u < 4; u++) {
        int j = tid + u * 256;
        float v = acc[u];
        __nv_bfloat16 hi = __float2bfloat16(v);
        __nv_bfloat16 lo = __float2bfloat16(v - __bfloat162float(hi));
        Rbig[base + j] = hi;
        Rbig[base + HID + j] = lo;
        Rbig[base + 2 * HID + j] = hi;
    }
}

// ---------------------------------------------------------------------------
// Heads
// ---------------------------------------------------------------------------
__global__ void ghost_kernel(const float* __restrict__ t, const float* __restrict__ gw2,
                             const float* __restrict__ gb2, float* __restrict__ out) {
    int warp = (blockIdx.x * blockDim.x + threadIdx.x) >> 5;
    int lane = threadIdx.x & 31;
    if (warp >= NN) return;
    float s = 0.f;
#pragma unroll
    for (int k = lane; k < 256; k += 32) s = fmaf(t[(size_t)warp * 256 + k], gw2[k], s);
#pragma unroll
    for (int o = 16; o; o >>= 1) s += __shfl_xor_sync(0xFFFFFFFFu, s, o);
    if (lane == 0) out[warp] = 1.f / (1.f + expf(-(s + gb2[0])));
}
__global__ void stable_kernel(const float* __restrict__ h, const float* __restrict__ sw,
                              const float* __restrict__ sb, float* __restrict__ out) {
    int n    = blockIdx.x;
    int c    = threadIdx.y;
    int lane = threadIdx.x;
    float s  = 0.f;
    for (int k = lane; k < HID; k += 32) s = fmaf(h[(size_t)n * HID + k], sw[k * SD + c], s);
#pragma unroll
    for (int o = 16; o; o >>= 1) s += __shfl_xor_sync(0xFFFFFFFFu, s, o);
    if (lane == 0) out[(size_t)n * SD + c] = s + sb[c];
}
__global__ void copy_kernel(const float* __restrict__ src, float* __restrict__ dst, int n) {
    int i = blockIdx.x * blockDim.x + threadIdx.x;
    if (i < n) dst[i] = src[i];
}

// ---------------------------------------------------------------------------
// Launch
// ---------------------------------------------------------------------------
extern "C" void kernel_launch(void* const* d_in, const int* in_sizes, int n_in,
                              void* d_out, int out_size) {
    const float* x      = (const float*)d_in[0];
    const int*   eidx   = (const int*)  d_in[1];
    const float* proj_w = (const float*)d_in[2];
    const float* W1     = (const float*)d_in[3];
    const float* b1     = (const float*)d_in[4];
    const float* W2     = (const float*)d_in[5];
    const float* b2     = (const float*)d_in[6];
    const float* gw1    = (const float*)d_in[7];
    const float* gb1    = (const float*)d_in[8];
    const float* gw2    = (const float*)d_in[9];
    const float* gb2    = (const float*)d_in[10];
    const float* sw     = (const float*)d_in[11];
    const float* sb     = (const float*)d_in[12];
    float* out = (float*)d_out;

    const int* e_src = eidx;
    const int* e_dst = eidx + EE;

    float *p_h, *p_HAB, *p_t;
    __nv_bfloat16 *p_Abig, *p_Rbig, *p_WtAB, *p_WtW2, *p_WtG;
    int *p_deg, *p_off, *p_cur, *p_srcs;
    cudaGetSymbolAddress((void**)&p_h,    g_h);
    cudaGetSymbolAddress((void**)&p_HAB,  g_HAB);
    cudaGetSymbolAddress((void**)&p_t,    g_t);
    cudaGetSymbolAddress((void**)&p_Abig, g_Abig);
    cudaGetSymbolAddress((void**)&p_Rbig, g_Rbig);
    cudaGetSymbolAddress((void**)&p_WtAB, g_WtAB);
    cudaGetSymbolAddress((void**)&p_WtW2, g_WtW2);
    cudaGetSymbolAddress((void**)&p_WtG,  g_WtG);
    cudaGetSymbolAddress((void**)&p_deg,  g_deg);
    cudaGetSymbolAddress((void**)&p_off,  g_off);
    cudaGetSymbolAddress((void**)&p_cur,  g_cur);
    cudaGetSymbolAddress((void**)&p_srcs, g_srcs);

    cudaFuncSetAttribute(mma_gemm<0>, cudaFuncAttributeMaxDynamicSharedMemorySize, MM_SMEM);
    cudaFuncSetAttribute(mma_gemm<1>, cudaFuncAttributeMaxDynamicSharedMemorySize, MM_SMEM);
    cudaFuncSetAttribute(mma_gemm<2>, cudaFuncAttributeMaxDynamicSharedMemorySize, MM_SMEM);

    const size_t KK = (size_t)HID * HID;

    // 1) Weight conversions (transpose + bf16 split)
    dim3 cb(32, 8);
    dim3 cg(HID / 32, HID / 32);
    dim3 cgh(256 / 32, HID / 32);
    for (int l = 0; l < LAYERS; l++) {
        const float* W1a = W1 + (size_t)l * 2 * KK;
        const float* W1b = W1a + KK;
        __nv_bfloat16* WtAB = p_WtAB + (size_t)l * 2048 * K3;
        convW_kernel<<<cg, cb>>>(W1a, W1b, WtAB, HID);                       // rows 0..1023: A = W1a - W1b
        convW_kernel<<<cg, cb>>>(W1b, nullptr, WtAB + (size_t)1024 * K3, HID); // rows 1024..2047: B
        convW_kernel<<<cg, cb>>>(W2 + (size_t)l * KK, nullptr, p_WtW2 + (size_t)l * HID * K3, HID);
    }
    convW_kernel<<<cgh, cb>>>(gw1, nullptr, p_WtG, 256);

    // 2) CSR build
    zero_int_kernel<<<(NN + 255) / 256, 256>>>(p_deg, NN);
    hist_kernel<<<(EE + 255) / 256, 256>>>(e_dst, p_deg);
    scan_kernel<<<1, 1024>>>(p_deg, p_off);
    copy_off_kernel<<<(NN + 255) / 256, 256>>>(p_off, p_cur);
    scatter_kernel<<<(EE + 255) / 256, 256>>>(e_src, e_dst, p_cur, p_srcs);
    sort_kernel<<<(NN + 255) / 256, 256>>>(p_off, p_srcs);

    // 3) Phase embedding -> Abig (split bf16)
    proj_kernel<<<(NN * HID + 255) / 256, 256>>>(x, proj_w, p_Abig);

    // 4) Layers
    const int NBM = (NN + BM - 1) / BM;      // 79
    dim3 gAB(2048 / BN, NBM);                // (16, 79)
    dim3 gW2(HID / BN, NBM);                 // (8, 79)
    for (int l = 0; l < LAYERS; l++) {
        const __nv_bfloat16* WtAB = p_WtAB + (size_t)l * 2048 * K3;
        const __nv_bfloat16* WtW2 = p_WtW2 + (size_t)l * HID * K3;
        const float* b1l = b1 + (size_t)l * HID;
        const float* b2l = b2 + (size_t)l * HID;

        mma_gemm<0><<<gAB, 256, MM_SMEM>>>(p_Abig, WtAB, p_HAB, NN, 2048, nullptr, nullptr, nullptr);
        edge_agg_kernel<<<NN, 256>>>(p_HAB, p_off, p_srcs, b1l, p_Rbig);
        mma_gemm<1><<<gW2, 256, MM_SMEM>>>(p_Rbig, WtW2, p_h, NN, HID, b2l, p_deg, p_Abig);
    }

    // 5) Heads
    dim3 ghead(256 / BN, NBM);               // (2, 79)
    mma_gemm<2><<<ghead, 256, MM_SMEM>>>(p_Abig, p_WtG, p_t, NN, 256, gb1, nullptr, nullptr);
    ghost_kernel<<<(NN * 32 + 255) / 256, 256>>>(p_t, gw2, gb2, out);
    stable_kernel<<<NN, dim3(32, SD)>>>(p_h, sw, sb, out + NN);
    copy_kernel<<<(NN * HID + 255) / 256, 256>>>(p_h, out + NN + NN * SD, NN * HID);
}

// round 6
// speedup vs baseline: 2.4759x; 1.1382x over previous
#include <cuda_runtime.h>
#include <cuda_bf16.h>
#include <math.h>
#include <stdint.h>

// Problem constants
#define NN   10000
#define EE   80000
#define SD   18
#define HID  1024
#define K3   3072          // split-K: [hi | lo | hi] x [whi | whi | wlo]
#define LAYERS 4

// GEMM tiling: BM=BN=128, BK=32, 128 threads (4 warps, 2x2 grid of 64x64 warp tiles)
#define BM 128
#define BN 128
#define BK 32
#define STG 4
#define NK (K3 / BK)               // 96
#define PADB 80                    // padded smem row stride in bytes (40 bf16)
#define TILE_BYTES (128 * PADB)    // 10240
#define STAGE_BYTES (2 * TILE_BYTES)
#define MM_SMEM (STG * STAGE_BYTES)   // 81920

// ---------------------------------------------------------------------------
// Scratch (device globals — no runtime allocation allowed)
// ---------------------------------------------------------------------------
__device__ float g_h  [NN * HID];
__device__ float g_HAB[NN * 2048];
__device__ float g_t  [NN * 256];
__device__ __nv_bfloat16 g_Abig[NN * K3];
__device__ __nv_bfloat16 g_Rbig[NN * K3];
__device__ __nv_bfloat16 g_WtAB[LAYERS * 2048 * K3];
__device__ __nv_bfloat16 g_WtW2[LAYERS * HID * K3];
__device__ __nv_bfloat16 g_WtG [256 * K3];
__device__ int   g_deg[NN];
__device__ int   g_off[NN + 1];
__device__ int   g_cur[NN];
__device__ int   g_srcs[EE];

// ---------------------------------------------------------------------------
// PTX helpers (baseline ISA only: cp.async / ldmatrix / mma.sync)
// ---------------------------------------------------------------------------
__device__ __forceinline__ uint32_t smem_u32(const void* p) {
    uint32_t a;
    asm("{ .reg .u64 t; cvta.to.shared.u64 t, %1; cvt.u32.u64 %0, t; }" : "=r"(a) : "l"(p));
    return a;
}
__device__ __forceinline__ void cp16(uint32_t dst, const void* src, bool valid) {
    int sz = valid ? 16 : 0;
    asm volatile("cp.async.cg.shared.global [%0], [%1], 16, %2;" :: "r"(dst), "l"(src), "r"(sz) : "memory");
}
__device__ __forceinline__ void cp_commit() { asm volatile("cp.async.commit_group;" ::: "memory"); }
__device__ __forceinline__ void ldm_x4(uint32_t& r0, uint32_t& r1, uint32_t& r2, uint32_t& r3,
                                       uint32_t addr) {
    asm volatile("ldmatrix.sync.aligned.m8n8.x4.shared.b16 {%0,%1,%2,%3}, [%4];"
                 : "=r"(r0), "=r"(r1), "=r"(r2), "=r"(r3) : "r"(addr));
}
__device__ __forceinline__ void mma_bf16(float& c0, float& c1, float& c2, float& c3,
                                         uint32_t a0, uint32_t a1, uint32_t a2, uint32_t a3,
                                         uint32_t b0, uint32_t b1) {
    asm volatile(
        "mma.sync.aligned.m16n8k16.row.col.f32.bf16.bf16.f32 "
        "{%0,%1,%2,%3}, {%4,%5,%6,%7}, {%8,%9}, {%0,%1,%2,%3};"
        : "+f"(c0), "+f"(c1), "+f"(c2), "+f"(c3)
        : "r"(a0), "r"(a1), "r"(a2), "r"(a3), "r"(b0), "r"(b1));
}

// ---------------------------------------------------------------------------
// HMMA GEMM: C[M, Nstride] = A[M, K3] @ Bt[N, K3]^T  (bf16 in, fp32 out)
// MODE 0: plain
// MODE 1: v = relu(acc + deg[row]*bias[col]); writes C (fp32) AND abig split
// MODE 2: relu(acc + bias[col])
// 128 threads, 4 warps in 2(M) x 2(N); warp tile 64x64; frag m16n8k16.
// Balance: per k16 a warp does 8 ldmatrix.x4 (4KB) for 32 MMA (131072 FLOP)
// = 32 FLOP/smem-byte = the SM's HMMA/LDS balance point.
// ---------------------------------------------------------------------------
template <int MODE>
__global__ void __launch_bounds__(128)
mma_gemm(const __nv_bfloat16* __restrict__ A, const __nv_bfloat16* __restrict__ Bt,
         float* __restrict__ C, int M, int Nstride,
         const float* __restrict__ bias, const int* __restrict__ deg,
         __nv_bfloat16* __restrict__ abig) {
    extern __shared__ char smem[];
    const uint32_t sb = smem_u32(smem);
    const int tid  = threadIdx.x;
    const int wid  = tid >> 5;
    const int lane = tid & 31;
    const int bm   = blockIdx.y * BM;
    const int bn   = blockIdx.x * BN;
    const int warp_m = (wid & 1) * 64;
    const int warp_n = (wid >> 1) * 64;

    // cp.async mapping: chunk c in [0,512): row=c>>2, col16=c&3.
    // 128 threads -> each thread owns c = tid + {0,128,256,384} per operand.
    const char* gA = (const char*)A  + (size_t)bm * (K3 * 2);
    const char* gB = (const char*)Bt + (size_t)bn * (K3 * 2);
    int  rr[4]; int cc[4]; bool avv[4];
#pragma unroll
    for (int u = 0; u < 4; u++) {
        int c = tid + u * 128;
        rr[u] = c >> 2;
        cc[u] = (c & 3) * 16;
        avv[u] = (bm + rr[u]) < M;
    }

    auto load_chunk = [&](int kc, int s) {
        uint32_t sa = sb + s * STAGE_BYTES;
        uint32_t sB = sa + TILE_BYTES;
        size_t kb = (size_t)kc * (BK * 2);
#pragma unroll
        for (int u = 0; u < 4; u++) {
            cp16(sa + rr[u] * PADB + cc[u], gA + (size_t)rr[u] * (K3 * 2) + kb + cc[u], avv[u]);
            cp16(sB + rr[u] * PADB + cc[u], gB + (size_t)rr[u] * (K3 * 2) + kb + cc[u], true);
        }
        cp_commit();
    };

    // ldmatrix lane-offset patterns
    const int g  = lane >> 3;
    const int lr = lane & 7;
    const int A_lane = ((g & 1) * 8 + lr) * PADB + (g >> 1) * 16;   // bytes
    const int B_lane = ((g >> 1) * 8 + lr) * PADB + (g & 1) * 16;   // bytes

    float acc[4][8][4];
#pragma unroll
    for (int i = 0; i < 4; i++)
#pragma unroll
        for (int j = 0; j < 8; j++)
#pragma unroll
            for (int q = 0; q < 4; q++) acc[i][j][q] = 0.f;

    // prologue
#pragma unroll
    for (int s = 0; s < STG - 1; s++) load_chunk(s, s);

    for (int it = 0; it < NK; it++) {
        asm volatile("cp.async.wait_group %0;" :: "n"(STG - 2) : "memory");
        __syncthreads();
        int cl = it + STG - 1;
        if (cl < NK) load_chunk(cl, cl % STG);
        else         cp_commit();      // empty group keeps wait_group bookkeeping valid

        uint32_t sa = sb + (it % STG) * STAGE_BYTES;
        uint32_t sB = sa + TILE_BYTES;
#pragma unroll
        for (int kk = 0; kk < 2; kk++) {
            uint32_t a[4][4], b[4][4];
#pragma unroll
            for (int mt = 0; mt < 4; mt++)
                ldm_x4(a[mt][0], a[mt][1], a[mt][2], a[mt][3],
                       sa + (warp_m + mt * 16) * PADB + kk * 32 + A_lane);
#pragma unroll
            for (int nt2 = 0; nt2 < 4; nt2++)
                ldm_x4(b[nt2][0], b[nt2][1], b[nt2][2], b[nt2][3],
                       sB + (warp_n + nt2 * 16) * PADB + kk * 32 + B_lane);
#pragma unroll
            for (int mt = 0; mt < 4; mt++)
#pragma unroll
                for (int nt = 0; nt < 8; nt++) {
                    uint32_t bb0 = b[nt >> 1][(nt & 1) * 2 + 0];
                    uint32_t bb1 = b[nt >> 1][(nt & 1) * 2 + 1];
                    mma_bf16(acc[mt][nt][0], acc[mt][nt][1], acc[mt][nt][2], acc[mt][nt][3],
                             a[mt][0], a[mt][1], a[mt][2], a[mt][3], bb0, bb1);
                }
        }
        __syncthreads();
    }

    // epilogue
    const int tq = lane >> 2;      // 0..7
    const int tr = lane & 3;       // 0..3
#pragma unroll
    for (int mt = 0; mt < 4; mt++) {
#pragma unroll
        for (int half = 0; half < 2; half++) {
            int row = bm + warp_m + mt * 16 + half * 8 + tq;
            if (row >= M) continue;
            float degf = 0.f;
            if (MODE == 1) degf = (float)deg[row];
#pragma unroll
            for (int nt = 0; nt < 8; nt++) {
                int col = bn + warp_n + nt * 8 + tr * 2;
                float vx = acc[mt][nt][half * 2 + 0];
                float vy = acc[mt][nt][half * 2 + 1];
                if (MODE == 1) {
                    vx = fmaxf(fmaf(degf, bias[col + 0], vx), 0.f);
                    vy = fmaxf(fmaf(degf, bias[col + 1], vy), 0.f);
                } else if (MODE == 2) {
                    vx = fmaxf(vx + bias[col + 0], 0.f);
                    vy = fmaxf(vy + bias[col + 1], 0.f);
                }
                *reinterpret_cast<float2*>(&C[(size_t)row * Nstride + col]) = make_float2(vx, vy);
                if (MODE == 1) {
                    __nv_bfloat162 hi2, lo2;
                    hi2.x = __float2bfloat16(vx);
                    hi2.y = __float2bfloat16(vy);
                    lo2.x = __float2bfloat16(vx - __bfloat162float(hi2.x));
                    lo2.y = __float2bfloat16(vy - __bfloat162float(hi2.y));
                    size_t base = (size_t)row * K3 + col;
                    *reinterpret_cast<__nv_bfloat162*>(&abig[base])            = hi2;
                    *reinterpret_cast<__nv_bfloat162*>(&abig[base + HID])      = lo2;
                    *reinterpret_cast<__nv_bfloat162*>(&abig[base + 2 * HID])  = hi2;
                }
            }
        }
    }
}

// ---------------------------------------------------------------------------
// Weight transpose + bf16 split: out[n][0:K]=hi, [K:2K]=hi, [2K:3K]=lo
// W is [K=1024, N] row-major (optionally Wa - Wb)
// ---------------------------------------------------------------------------
__global__ void convW_kernel(const float* __restrict__ Wa, const float* __restrict__ Wb,
                             __nv_bfloat16* __restrict__ out, int N) {
    __shared__ float t[32][33];
    int n0 = blockIdx.x * 32, k0 = blockIdx.y * 32;
    int tx = threadIdx.x, ty = threadIdx.y;
#pragma unroll
    for (int r = ty; r < 32; r += 8) {
        float v = Wa[(size_t)(k0 + r) * N + n0 + tx];
        if (Wb) v -= Wb[(size_t)(k0 + r) * N + n0 + tx];
        t[r][tx] = v;
    }
    __syncthreads();
#pragma unroll
    for (int r = ty; r < 32; r += 8) {
        int n = n0 + r, k = k0 + tx;
        float v = t[tx][r];
        __nv_bfloat16 hi = __float2bfloat16(v);
        __nv_bfloat16 lo = __float2bfloat16(v - __bfloat162float(hi));
        size_t base = (size_t)n * K3;
        out[base + k] = hi;
        out[base + HID + k] = hi;
        out[base + 2 * HID + k] = lo;
    }
}

// ---------------------------------------------------------------------------
// CSR build (deterministic)
// ---------------------------------------------------------------------------
__global__ void zero_int_kernel(int* p, int n) {
    int i = blockIdx.x * blockDim.x + threadIdx.x;
    if (i < n) p[i] = 0;
}
__global__ void hist_kernel(const int* __restrict__ dst, int* __restrict__ deg) {
    int e = blockIdx.x * blockDim.x + threadIdx.x;
    if (e < EE) atomicAdd(&deg[dst[e]], 1);
}
__global__ void scan_kernel(const int* __restrict__ deg, int* __restrict__ off) {
    __shared__ int sh[1024];
    __shared__ int carry;
    if (threadIdx.x == 0) { carry = 0; off[0] = 0; }
    __syncthreads();
    for (int start = 0; start < NN; start += 1024) {
        int i = start + threadIdx.x;
        int v = (i < NN) ? deg[i] : 0;
        sh[threadIdx.x] = v;
        __syncthreads();
        for (int d = 1; d < 1024; d <<= 1) {
            int t = (threadIdx.x >= d) ? sh[threadIdx.x - d] : 0;
            __syncthreads();
            sh[threadIdx.x] += t;
            __syncthreads();
        }
        if (i < NN) off[i + 1] = carry + sh[threadIdx.x];
        __syncthreads();
        if (threadIdx.x == 1023) carry += sh[1023];
        __syncthreads();
    }
}
__global__ void copy_off_kernel(const int* __restrict__ off, int* __restrict__ cur) {
    int i = blockIdx.x * blockDim.x + threadIdx.x;
    if (i < NN) cur[i] = off[i];
}
__global__ void scatter_kernel(const int* __restrict__ src, const int* __restrict__ dst,
                               int* __restrict__ cur, int* __restrict__ srcs) {
    int e = blockIdx.x * blockDim.x + threadIdx.x;
    if (e < EE) {
        int p = atomicAdd(&cur[dst[e]], 1);
        srcs[p] = src[e];
    }
}
__global__ void sort_kernel(const int* __restrict__ off, int* __restrict__ srcs) {
    int i = blockIdx.x * blockDim.x + threadIdx.x;
    if (i >= NN) return;
    int a = off[i], b = off[i + 1];
    for (int x = a + 1; x < b; x++) {
        int v = srcs[x];
        int y = x - 1;
        while (y >= a && srcs[y] > v) { srcs[y + 1] = srcs[y]; y--; }
        srcs[y + 1] = v;
    }
}

// ---------------------------------------------------------------------------
// Phase embedding: writes split-bf16 Abig directly
// ---------------------------------------------------------------------------
__global__ void proj_kernel(const float* __restrict__ x, const float* __restrict__ pw,
                            __nv_bfloat16* __restrict__ Abig) {
    int idx = blockIdx.x * blockDim.x + threadIdx.x;
    if (idx >= NN * HID) return;
    int n = idx >> 10, j = idx & (HID - 1);
    float p = 0.f;
#pragma unroll
    for (int k = 0; k < SD; k++) p = fmaf(x[n * SD + k], pw[k * HID + j], p);
    float v = sinf(p) * cosf(p);
    __nv_bfloat16 hi = __float2bfloat16(v);
    __nv_bfloat16 lo = __float2bfloat16(v - __bfloat162float(hi));
    size_t base = (size_t)n * K3;
    Abig[base + j] = hi;
    Abig[base + HID + j] = lo;
    Abig[base + 2 * HID + j] = hi;
}

// ---------------------------------------------------------------------------
// Edge aggregation: R[i] = sum relu(HA[i] + HB[src] + b1); writes split bf16
// HAB layout: row n holds [HA(n) | HB(n)] (2048 floats)
// ---------------------------------------------------------------------------
__global__ void edge_agg_kernel(const float* __restrict__ HAB,
                                const int* __restrict__ off, const int* __restrict__ srcs,
                                const float* __restrict__ b1, __nv_bfloat16* __restrict__ Rbig) {
    int i   = blockIdx.x;
    int tid = threadIdx.x;
    float ha[4], acc[4];
#pragma unroll
    for (int u = 0; u < 4; u++) {
        int j  = tid + u * 256;
        ha[u]  = HAB[(size_t)i * 2048 + j] + b1[j];
        acc[u] = 0.f;
    }
    int s0 = off[i], s1 = off[i + 1];
    for (int e = s0; e < s1; e++) {
        int s = srcs[e];
        const float* hb = HAB + (size_t)s * 2048 + 1024;
#pragma unroll
        for (int u = 0; u < 4; u++) acc[u] += fmaxf(ha[u] + hb[tid + u * 256], 0.f);
    }
    size_t base = (size_t)i * K3;
#pragma unroll
    for (int u = 0; u < 4; u++) {
        int j = tid + u * 256;
        float v = acc[u];
        __nv_bfloat16 hi = __float2bfloat16(v);
        __nv_bfloat16 lo = __float2bfloat16(v - __bfloat162float(hi));
        Rbig[base + j] = hi;
        Rbig[base + HID + j] = lo;
        Rbig[base + 2 * HID + j] = hi;
    }
}

// ---------------------------------------------------------------------------
// Heads
// ---------------------------------------------------------------------------
__global__ void ghost_kernel(const float* __restrict__ t, const float* __restrict__ gw2,
                             const float* __restrict__ gb2, float* __restrict__ out) {
    int warp = (blockIdx.x * blockDim.x + threadIdx.x) >> 5;
    int lane = threadIdx.x & 31;
    if (warp >= NN) return;
    float s = 0.f;
#pragma unroll
    for (int k = lane; k < 256; k += 32) s = fmaf(t[(size_t)warp * 256 + k], gw2[k], s);
#pragma unroll
    for (int o = 16; o; o >>= 1) s += __shfl_xor_sync(0xFFFFFFFFu, s, o);
    if (lane == 0) out[warp] = 1.f / (1.f + expf(-(s + gb2[0])));
}
__global__ void stable_kernel(const float* __restrict__ h, const float* __restrict__ sw,
                              const float* __restrict__ sb, float* __restrict__ out) {
    int n    = blockIdx.x;
    int c    = threadIdx.y;
    int lane = threadIdx.x;
    float s  = 0.f;
    for (int k = lane; k < HID; k += 32) s = fmaf(h[(size_t)n * HID + k], sw[k * SD + c], s);
#pragma unroll
    for (int o = 16; o; o >>= 1) s += __shfl_xor_sync(0xFFFFFFFFu, s, o);
    if (lane == 0) out[(size_t)n * SD + c] = s + sb[c];
}
__global__ void copy_kernel(const float* __restrict__ src, float* __restrict__ dst, int n) {
    int i = blockIdx.x * blockDim.x + threadIdx.x;
    if (i < n) dst[i] = src[i];
}

// ---------------------------------------------------------------------------
// Launch
// ---------------------------------------------------------------------------
extern "C" void kernel_launch(void* const* d_in, const int* in_sizes, int n_in,
                              void* d_out, int out_size) {
    const float* x      = (const float*)d_in[0];
    const int*   eidx   = (const int*)  d_in[1];
    const float* proj_w = (const float*)d_in[2];
    const float* W1     = (const float*)d_in[3];
    const float* b1     = (const float*)d_in[4];
    const float* W2     = (const float*)d_in[5];
    const float* b2     = (const float*)d_in[6];
    const float* gw1    = (const float*)d_in[7];
    const float* gb1    = (const float*)d_in[8];
    const float* gw2    = (const float*)d_in[9];
    const float* gb2    = (const float*)d_in[10];
    const float* sw     = (const float*)d_in[11];
    const float* sb     = (const float*)d_in[12];
    float* out = (float*)d_out;

    const int* e_src = eidx;
    const int* e_dst = eidx + EE;

    float *p_h, *p_HAB, *p_t;
    __nv_bfloat16 *p_Abig, *p_Rbig, *p_WtAB, *p_WtW2, *p_WtG;
    int *p_deg, *p_off, *p_cur, *p_srcs;
    cudaGetSymbolAddress((void**)&p_h,    g_h);
    cudaGetSymbolAddress((void**)&p_HAB,  g_HAB);
    cudaGetSymbolAddress((void**)&p_t,    g_t);
    cudaGetSymbolAddress((void**)&p_Abig, g_Abig);
    cudaGetSymbolAddress((void**)&p_Rbig, g_Rbig);
    cudaGetSymbolAddress((void**)&p_WtAB, g_WtAB);
    cudaGetSymbolAddress((void**)&p_WtW2, g_WtW2);
    cudaGetSymbolAddress((void**)&p_WtG,  g_WtG);
    cudaGetSymbolAddress((void**)&p_deg,  g_deg);
    cudaGetSymbolAddress((void**)&p_off,  g_off);
    cudaGetSymbolAddress((void**)&p_cur,  g_cur);
    cudaGetSymbolAddress((void**)&p_srcs, g_srcs);

    cudaFuncSetAttribute(mma_gemm<0>, cudaFuncAttributeMaxDynamicSharedMemorySize, MM_SMEM);
    cudaFuncSetAttribute(mma_gemm<1>, cudaFuncAttributeMaxDynamicSharedMemorySize, MM_SMEM);
    cudaFuncSetAttribute(mma_gemm<2>, cudaFuncAttributeMaxDynamicSharedMemorySize, MM_SMEM);

    const size_t KK = (size_t)HID * HID;

    // 1) Weight conversions (transpose + bf16 split)
    dim3 cb(32, 8);
    dim3 cg(HID / 32, HID / 32);
    dim3 cgh(256 / 32, HID / 32);
    for (int l = 0; l < LAYERS; l++) {
        const float* W1a = W1 + (size_t)l * 2 * KK;
        const float* W1b = W1a + KK;
        __nv_bfloat16* WtAB = p_WtAB + (size_t)l * 2048 * K3;
        convW_kernel<<<cg, cb>>>(W1a, W1b, WtAB, HID);                         // rows 0..1023: A = W1a - W1b
        convW_kernel<<<cg, cb>>>(W1b, nullptr, WtAB + (size_t)1024 * K3, HID); // rows 1024..2047: B
        convW_kernel<<<cg, cb>>>(W2 + (size_t)l * KK, nullptr, p_WtW2 + (size_t)l * HID * K3, HID);
    }
    convW_kernel<<<cgh, cb>>>(gw1, nullptr, p_WtG, 256);

    // 2) CSR build
    zero_int_kernel<<<(NN + 255) / 256, 256>>>(p_deg, NN);
    hist_kernel<<<(EE + 255) / 256, 256>>>(e_dst, p_deg);
    scan_kernel<<<1, 1024>>>(p_deg, p_off);
    copy_off_kernel<<<(NN + 255) / 256, 256>>>(p_off, p_cur);
    scatter_kernel<<<(EE + 255) / 256, 256>>>(e_src, e_dst, p_cur, p_srcs);
    sort_kernel<<<(NN + 255) / 256, 256>>>(p_off, p_srcs);

    // 3) Phase embedding -> Abig (split bf16)
    proj_kernel<<<(NN * HID + 255) / 256, 256>>>(x, proj_w, p_Abig);

    // 4) Layers
    const int NBM = (NN + BM - 1) / BM;      // 79
    dim3 gAB(2048 / BN, NBM);                // (16, 79)
    dim3 gW2(HID / BN, NBM);                 // (8, 79)
    for (int l = 0; l < LAYERS; l++) {
        const __nv_bfloat16* WtAB = p_WtAB + (size_t)l * 2048 * K3;
        const __nv_bfloat16* WtW2 = p_WtW2 + (size_t)l * HID * K3;
        const float* b1l = b1 + (size_t)l * HID;
        const float* b2l = b2 + (size_t)l * HID;

        mma_gemm<0><<<gAB, 128, MM_SMEM>>>(p_Abig, WtAB, p_HAB, NN, 2048, nullptr, nullptr, nullptr);
        edge_agg_kernel<<<NN, 256>>>(p_HAB, p_off, p_srcs, b1l, p_Rbig);
        mma_gemm<1><<<gW2, 128, MM_SMEM>>>(p_Rbig, WtW2, p_h, NN, HID, b2l, p_deg, p_Abig);
    }

    // 5) Heads
    dim3 ghead(256 / BN, NBM);               // (2, 79)
    mma_gemm<2><<<ghead, 128, MM_SMEM>>>(p_Abig, p_WtG, p_t, NN, 256, gb1, nullptr, nullptr);
    ghost_kernel<<<(NN * 32 + 255) / 256, 256>>>(p_t, gw2, gb2, out);
    stable_kernel<<<NN, dim3(32, SD)>>>(p_h, sw, sb, out + NN);
    copy_kernel<<<(NN * HID + 255) / 256, 256>>>(p_h, out + NN + NN * SD, NN * HID);
}

// round 7
// speedup vs baseline: 2.6307x; 1.0625x over previous
#include <cuda_runtime.h>
#include <cuda_bf16.h>
#include <math.h>
#include <stdint.h>

// Problem constants
#define NN   10000
#define EE   80000
#define SD   18
#define HID  1024
#define K3   3072          // split-K: [hi | lo | hi] x [whi | whi | wlo]
#define LAYERS 4

// GEMM tiling: BM=BN=128, BK=32, 128 threads (4 warps, 2x2 grid of 64x64 warp tiles)
#define BM 128
#define BN 128
#define BK 32
#define STG 5
#define NK (K3 / BK)               // 96
#define PADB 80                    // padded smem row stride in bytes (40 bf16)
#define TILE_BYTES (128 * PADB)    // 10240
#define STAGE_BYTES (2 * TILE_BYTES)
#define MM_SMEM (STG * STAGE_BYTES)   // 102400

// ---------------------------------------------------------------------------
// Scratch (device globals — no runtime allocation allowed)
// ---------------------------------------------------------------------------
__device__ float g_h  [NN * HID];
__device__ float g_HAB[NN * 2048];
__device__ float g_t  [NN * 256];
__device__ __nv_bfloat16 g_Abig[NN * K3];
__device__ __nv_bfloat16 g_Rbig[NN * K3];
__device__ __nv_bfloat16 g_WtAB[LAYERS * 2048 * K3];
__device__ __nv_bfloat16 g_WtW2[LAYERS * HID * K3];
__device__ __nv_bfloat16 g_WtG [256 * K3];
__device__ int   g_deg[NN];
__device__ int   g_off[NN + 1];
__device__ int   g_cur[NN];
__device__ int   g_srcs[EE];

// ---------------------------------------------------------------------------
// PTX helpers (baseline ISA only: cp.async / ldmatrix / mma.sync)
// ---------------------------------------------------------------------------
__device__ __forceinline__ uint32_t smem_u32(const void* p) {
    uint32_t a;
    asm("{ .reg .u64 t; cvta.to.shared.u64 t, %1; cvt.u32.u64 %0, t; }" : "=r"(a) : "l"(p));
    return a;
}
__device__ __forceinline__ void cp16(uint32_t dst, const void* src, bool valid) {
    int sz = valid ? 16 : 0;
    asm volatile("cp.async.cg.shared.global [%0], [%1], 16, %2;" :: "r"(dst), "l"(src), "r"(sz) : "memory");
}
__device__ __forceinline__ void cp_commit() { asm volatile("cp.async.commit_group;" ::: "memory"); }
__device__ __forceinline__ void ldm_x4(uint32_t& r0, uint32_t& r1, uint32_t& r2, uint32_t& r3,
                                       uint32_t addr) {
    asm volatile("ldmatrix.sync.aligned.m8n8.x4.shared.b16 {%0,%1,%2,%3}, [%4];"
                 : "=r"(r0), "=r"(r1), "=r"(r2), "=r"(r3) : "r"(addr));
}
__device__ __forceinline__ void mma_bf16(float& c0, float& c1, float& c2, float& c3,
                                         uint32_t a0, uint32_t a1, uint32_t a2, uint32_t a3,
                                         uint32_t b0, uint32_t b1) {
    asm volatile(
        "mma.sync.aligned.m16n8k16.row.col.f32.bf16.bf16.f32 "
        "{%0,%1,%2,%3}, {%4,%5,%6,%7}, {%8,%9}, {%0,%1,%2,%3};"
        : "+f"(c0), "+f"(c1), "+f"(c2), "+f"(c3)
        : "r"(a0), "r"(a1), "r"(a2), "r"(a3), "r"(b0), "r"(b1));
}

// ---------------------------------------------------------------------------
// HMMA GEMM: C[M, Nstride] = A[M, K3] @ Bt[N, K3]^T  (bf16 in, fp32 out)
// MODE 0: plain
// MODE 1: v = relu(acc + deg[row]*bias[col]); writes C (fp32) AND abig split
// MODE 2: relu(acc + bias[col])
// 128 threads, 4 warps in 2(M) x 2(N); warp tile 64x64; frag m16n8k16.
// Single __syncthreads per iteration: the top-of-loop barrier (after
// wait_group) guarantees all warps finished iteration it-1 compute before
// any thread issues the load targeting slot (it-1)%STG.
// ---------------------------------------------------------------------------
template <int MODE>
__global__ void __launch_bounds__(128, 2)
mma_gemm(const __nv_bfloat16* __restrict__ A, const __nv_bfloat16* __restrict__ Bt,
         float* __restrict__ C, int M, int Nstride,
         const float* __restrict__ bias, const int* __restrict__ deg,
         __nv_bfloat16* __restrict__ abig) {
    extern __shared__ char smem[];
    const uint32_t sb = smem_u32(smem);
    const int tid  = threadIdx.x;
    const int wid  = tid >> 5;
    const int lane = tid & 31;
    const int bm   = blockIdx.y * BM;
    const int bn   = blockIdx.x * BN;
    const int warp_m = (wid & 1) * 64;
    const int warp_n = (wid >> 1) * 64;

    // cp.async mapping: chunk c in [0,512): row=c>>2, col16=c&3.
    const char* gA = (const char*)A  + (size_t)bm * (K3 * 2);
    const char* gB = (const char*)Bt + (size_t)bn * (K3 * 2);
    int  rr[4]; int cc[4]; bool avv[4];
#pragma unroll
    for (int u = 0; u < 4; u++) {
        int c = tid + u * 128;
        rr[u] = c >> 2;
        cc[u] = (c & 3) * 16;
        avv[u] = (bm + rr[u]) < M;
    }

    auto load_chunk = [&](int kc, int s) {
        uint32_t sa = sb + s * STAGE_BYTES;
        uint32_t sB = sa + TILE_BYTES;
        size_t kb = (size_t)kc * (BK * 2);
#pragma unroll
        for (int u = 0; u < 4; u++) {
            cp16(sa + rr[u] * PADB + cc[u], gA + (size_t)rr[u] * (K3 * 2) + kb + cc[u], avv[u]);
            cp16(sB + rr[u] * PADB + cc[u], gB + (size_t)rr[u] * (K3 * 2) + kb + cc[u], true);
        }
        cp_commit();
    };

    // ldmatrix lane-offset patterns
    const int g  = lane >> 3;
    const int lr = lane & 7;
    const int A_lane = ((g & 1) * 8 + lr) * PADB + (g >> 1) * 16;   // bytes
    const int B_lane = ((g >> 1) * 8 + lr) * PADB + (g & 1) * 16;   // bytes

    float acc[4][8][4];
#pragma unroll
    for (int i = 0; i < 4; i++)
#pragma unroll
        for (int j = 0; j < 8; j++)
#pragma unroll
            for (int q = 0; q < 4; q++) acc[i][j][q] = 0.f;

    // prologue
#pragma unroll
    for (int s = 0; s < STG - 1; s++) load_chunk(s, s);

    for (int it = 0; it < NK; it++) {
        asm volatile("cp.async.wait_group %0;" :: "n"(STG - 2) : "memory");
        __syncthreads();
        int cl = it + STG - 1;
        if (cl < NK) load_chunk(cl, cl % STG);
        else         cp_commit();      // empty group keeps wait_group bookkeeping valid

        uint32_t sa = sb + (it % STG) * STAGE_BYTES;
        uint32_t sB = sa + TILE_BYTES;
#pragma unroll
        for (int kk = 0; kk < 2; kk++) {
            uint32_t a[4][4], b[4][4];
#pragma unroll
            for (int mt = 0; mt < 4; mt++)
                ldm_x4(a[mt][0], a[mt][1], a[mt][2], a[mt][3],
                       sa + (warp_m + mt * 16) * PADB + kk * 32 + A_lane);
#pragma unroll
            for (int nt2 = 0; nt2 < 4; nt2++)
                ldm_x4(b[nt2][0], b[nt2][1], b[nt2][2], b[nt2][3],
                       sB + (warp_n + nt2 * 16) * PADB + kk * 32 + B_lane);
#pragma unroll
            for (int mt = 0; mt < 4; mt++)
#pragma unroll
                for (int nt = 0; nt < 8; nt++) {
                    uint32_t bb0 = b[nt >> 1][(nt & 1) * 2 + 0];
                    uint32_t bb1 = b[nt >> 1][(nt & 1) * 2 + 1];
                    mma_bf16(acc[mt][nt][0], acc[mt][nt][1], acc[mt][nt][2], acc[mt][nt][3],
                             a[mt][0], a[mt][1], a[mt][2], a[mt][3], bb0, bb1);
                }
        }
    }

    // epilogue (register-only inputs; no smem reads, no barrier needed)
    const int tq = lane >> 2;      // 0..7
    const int tr = lane & 3;       // 0..3
#pragma unroll
    for (int mt = 0; mt < 4; mt++) {
#pragma unroll
        for (int half = 0; half < 2; half++) {
            int row = bm + warp_m + mt * 16 + half * 8 + tq;
            if (row >= M) continue;
            float degf = 0.f;
            if (MODE == 1) degf = (float)deg[row];
#pragma unroll
            for (int nt = 0; nt < 8; nt++) {
                int col = bn + warp_n + nt * 8 + tr * 2;
                float vx = acc[mt][nt][half * 2 + 0];
                float vy = acc[mt][nt][half * 2 + 1];
                if (MODE == 1) {
                    vx = fmaxf(fmaf(degf, bias[col + 0], vx), 0.f);
                    vy = fmaxf(fmaf(degf, bias[col + 1], vy), 0.f);
                } else if (MODE == 2) {
                    vx = fmaxf(vx + bias[col + 0], 0.f);
                    vy = fmaxf(vy + bias[col + 1], 0.f);
                }
                *reinterpret_cast<float2*>(&C[(size_t)row * Nstride + col]) = make_float2(vx, vy);
                if (MODE == 1) {
                    __nv_bfloat162 hi2, lo2;
                    hi2.x = __float2bfloat16(vx);
                    hi2.y = __float2bfloat16(vy);
                    lo2.x = __float2bfloat16(vx - __bfloat162float(hi2.x));
                    lo2.y = __float2bfloat16(vy - __bfloat162float(hi2.y));
                    size_t base = (size_t)row * K3 + col;
                    *reinterpret_cast<__nv_bfloat162*>(&abig[base])            = hi2;
                    *reinterpret_cast<__nv_bfloat162*>(&abig[base + HID])      = lo2;
                    *reinterpret_cast<__nv_bfloat162*>(&abig[base + 2 * HID])  = hi2;
                }
            }
        }
    }
}

// ---------------------------------------------------------------------------
// Weight transpose + bf16 split: out[n][0:K]=hi, [K:2K]=hi, [2K:3K]=lo
// W is [K=1024, N] row-major (optionally Wa - Wb)
// ---------------------------------------------------------------------------
__global__ void convW_kernel(const float* __restrict__ Wa, const float* __restrict__ Wb,
                             __nv_bfloat16* __restrict__ out, int N) {
    __shared__ float t[32][33];
    int n0 = blockIdx.x * 32, k0 = blockIdx.y * 32;
    int tx = threadIdx.x, ty = threadIdx.y;
#pragma unroll
    for (int r = ty; r < 32; r += 8) {
        float v = Wa[(size_t)(k0 + r) * N + n0 + tx];
        if (Wb) v -= Wb[(size_t)(k0 + r) * N + n0 + tx];
        t[r][tx] = v;
    }
    __syncthreads();
#pragma unroll
    for (int r = ty; r < 32; r += 8) {
        int n = n0 + r, k = k0 + tx;
        float v = t[tx][r];
        __nv_bfloat16 hi = __float2bfloat16(v);
        __nv_bfloat16 lo = __float2bfloat16(v - __bfloat162float(hi));
        size_t base = (size_t)n * K3;
        out[base + k] = hi;
        out[base + HID + k] = hi;
        out[base + 2 * HID + k] = lo;
    }
}

// ---------------------------------------------------------------------------
// CSR build (deterministic)
// ---------------------------------------------------------------------------
__global__ void zero_int_kernel(int* p, int n) {
    int i = blockIdx.x * blockDim.x + threadIdx.x;
    if (i < n) p[i] = 0;
}
__global__ void hist_kernel(const int* __restrict__ dst, int* __restrict__ deg) {
    int e = blockIdx.x * blockDim.x + threadIdx.x;
    if (e < EE) atomicAdd(&deg[dst[e]], 1);
}
__global__ void scan_kernel(const int* __restrict__ deg, int* __restrict__ off) {
    __shared__ int sh[1024];
    __shared__ int carry;
    if (threadIdx.x == 0) { carry = 0; off[0] = 0; }
    __syncthreads();
    for (int start = 0; start < NN; start += 1024) {
        int i = start + threadIdx.x;
        int v = (i < NN) ? deg[i] : 0;
        sh[threadIdx.x] = v;
        __syncthreads();
        for (int d = 1; d < 1024; d <<= 1) {
            int t = (threadIdx.x >= d) ? sh[threadIdx.x - d] : 0;
            __syncthreads();
            sh[threadIdx.x] += t;
            __syncthreads();
        }
        if (i < NN) off[i + 1] = carry + sh[threadIdx.x];
        __syncthreads();
        if (threadIdx.x == 1023) carry += sh[1023];
        __syncthreads();
    }
}
__global__ void copy_off_kernel(const int* __restrict__ off, int* __restrict__ cur) {
    int i = blockIdx.x * blockDim.x + threadIdx.x;
    if (i < NN) cur[i] = off[i];
}
__global__ void scatter_kernel(const int* __restrict__ src, const int* __restrict__ dst,
                               int* __restrict__ cur, int* __restrict__ srcs) {
    int e = blockIdx.x * blockDim.x + threadIdx.x;
    if (e < EE) {
        int p = atomicAdd(&cur[dst[e]], 1);
        srcs[p] = src[e];
    }
}
__global__ void sort_kernel(const int* __restrict__ off, int* __restrict__ srcs) {
    int i = blockIdx.x * blockDim.x + threadIdx.x;
    if (i >= NN) return;
    int a = off[i], b = off[i + 1];
    for (int x = a + 1; x < b; x++) {
        int v = srcs[x];
        int y = x - 1;
        while (y >= a && srcs[y] > v) { srcs[y + 1] = srcs[y]; y--; }
        srcs[y + 1] = v;
    }
}

// ---------------------------------------------------------------------------
// Phase embedding: writes split-bf16 Abig directly
// ---------------------------------------------------------------------------
__global__ void proj_kernel(const float* __restrict__ x, const float* __restrict__ pw,
                            __nv_bfloat16* __restrict__ Abig) {
    int idx = blockIdx.x * blockDim.x + threadIdx.x;
    if (idx >= NN * HID) return;
    int n = idx >> 10, j = idx & (HID - 1);
    float p = 0.f;
#pragma unroll
    for (int k = 0; k < SD; k++) p = fmaf(x[n * SD + k], pw[k * HID + j], p);
    float v = sinf(p) * cosf(p);
    __nv_bfloat16 hi = __float2bfloat16(v);
    __nv_bfloat16 lo = __float2bfloat16(v - __bfloat162float(hi));
    size_t base = (size_t)n * K3;
    Abig[base + j] = hi;
    Abig[base + HID + j] = lo;
    Abig[base + 2 * HID + j] = hi;
}

// ---------------------------------------------------------------------------
// Edge aggregation: R[i] = sum relu(HA[i] + HB[src] + b1); writes split bf16
// HAB layout: row n holds [HA(n) | HB(n)] (2048 floats)
// ---------------------------------------------------------------------------
__global__ void edge_agg_kernel(const float* __restrict__ HAB,
                                const int* __restrict__ off, const int* __restrict__ srcs,
                                const float* __restrict__ b1, __nv_bfloat16* __restrict__ Rbig) {
    int i   = blockIdx.x;
    int tid = threadIdx.x;
    float ha[4], acc[4];
#pragma unroll
    for (int u = 0; u < 4; u++) {
        int j  = tid + u * 256;
        ha[u]  = HAB[(size_t)i * 2048 + j] + b1[j];
        acc[u] = 0.f;
    }
    int s0 = off[i], s1 = off[i + 1];
    for (int e = s0; e < s1; e++) {
        int s = srcs[e];
        const float* hb = HAB + (size_t)s * 2048 + 1024;
#pragma unroll
        for (int u = 0; u < 4; u++) acc[u] += fmaxf(ha[u] + hb[tid + u * 256], 0.f);
    }
    size_t base = (size_t)i * K3;
#pragma unroll
    for (int u = 0; u < 4; u++) {
        int j = tid + u * 256;
        float v = acc[u];
        __nv_bfloat16 hi = __float2bfloat16(v);
        __nv_bfloat16 lo = __float2bfloat16(v - __bfloat162float(hi));
        Rbig[base + j] = hi;
        Rbig[base + HID + j] = lo;
        Rbig[base + 2 * HID + j] = hi;
    }
}

// ---------------------------------------------------------------------------
// Heads
// ---------------------------------------------------------------------------
__global__ void ghost_kernel(const float* __restrict__ t, const float* __restrict__ gw2,
                             const float* __restrict__ gb2, float* __restrict__ out) {
    int warp = (blockIdx.x * blockDim.x + threadIdx.x) >> 5;
    int lane = threadIdx.x & 31;
    if (warp >= NN) return;
    float s = 0.f;
#pragma unroll
    for (int k = lane; k < 256; k += 32) s = fmaf(t[(size_t)warp * 256 + k], gw2[k], s);
#pragma unroll
    for (int o = 16; o; o >>= 1) s += __shfl_xor_sync(0xFFFFFFFFu, s, o);
    if (lane == 0) out[warp] = 1.f / (1.f + expf(-(s + gb2[0])));
}
__global__ void stable_kernel(const float* __restrict__ h, const float* __restrict__ sw,
                              const float* __restrict__ sb, float* __restrict__ out) {
    int n    = blockIdx.x;
    int c    = threadIdx.y;
    int lane = threadIdx.x;
    float s  = 0.f;
    for (int k = lane; k < HID; k += 32) s = fmaf(h[(size_t)n * HID + k], sw[k * SD + c], s);
#pragma unroll
    for (int o = 16; o; o >>= 1) s += __shfl_xor_sync(0xFFFFFFFFu, s, o);
    if (lane == 0) out[(size_t)n * SD + c] = s + sb[c];
}

// ---------------------------------------------------------------------------
// Launch
// Stream order is arranged so launch index 5 (0-based) is the layer-0 AB
// GEMM: ncu's "-s 5 -c 1" then profiles the dominant kernel.
// ---------------------------------------------------------------------------
extern "C" void kernel_launch(void* const* d_in, const int* in_sizes, int n_in,
                              void* d_out, int out_size) {
    const float* x      = (const float*)d_in[0];
    const int*   eidx   = (const int*)  d_in[1];
    const float* proj_w = (const float*)d_in[2];
    const float* W1     = (const float*)d_in[3];
    const float* b1     = (const float*)d_in[4];
    const float* W2     = (const float*)d_in[5];
    const float* b2     = (const float*)d_in[6];
    const float* gw1    = (const float*)d_in[7];
    const float* gb1    = (const float*)d_in[8];
    const float* gw2    = (const float*)d_in[9];
    const float* gb2    = (const float*)d_in[10];
    const float* sw     = (const float*)d_in[11];
    const float* sb     = (const float*)d_in[12];
    float* out = (float*)d_out;

    const int* e_src = eidx;
    const int* e_dst = eidx + EE;

    float *p_h, *p_HAB, *p_t;
    __nv_bfloat16 *p_Abig, *p_Rbig, *p_WtAB, *p_WtW2, *p_WtG;
    int *p_deg, *p_off, *p_cur, *p_srcs;
    cudaGetSymbolAddress((void**)&p_h,    g_h);
    cudaGetSymbolAddress((void**)&p_HAB,  g_HAB);
    cudaGetSymbolAddress((void**)&p_t,    g_t);
    cudaGetSymbolAddress((void**)&p_Abig, g_Abig);
    cudaGetSymbolAddress((void**)&p_Rbig, g_Rbig);
    cudaGetSymbolAddress((void**)&p_WtAB, g_WtAB);
    cudaGetSymbolAddress((void**)&p_WtW2, g_WtW2);
    cudaGetSymbolAddress((void**)&p_WtG,  g_WtG);
    cudaGetSymbolAddress((void**)&p_deg,  g_deg);
    cudaGetSymbolAddress((void**)&p_off,  g_off);
    cudaGetSymbolAddress((void**)&p_cur,  g_cur);
    cudaGetSymbolAddress((void**)&p_srcs, g_srcs);

    cudaFuncSetAttribute(mma_gemm<0>, cudaFuncAttributeMaxDynamicSharedMemorySize, MM_SMEM);
    cudaFuncSetAttribute(mma_gemm<1>, cudaFuncAttributeMaxDynamicSharedMemorySize, MM_SMEM);
    cudaFuncSetAttribute(mma_gemm<2>, cudaFuncAttributeMaxDynamicSharedMemorySize, MM_SMEM);

    const size_t KK = (size_t)HID * HID;
    dim3 cb(32, 8);
    dim3 cg(HID / 32, HID / 32);
    dim3 cgh(256 / 32, HID / 32);
    const int NBM = (NN + BM - 1) / BM;      // 79
    dim3 gAB(2048 / BN, NBM);                // (16, 79)
    dim3 gW2(HID / BN, NBM);                 // (8, 79)
    dim3 ghead(256 / BN, NBM);               // (2, 79)
    float* h_last = out + NN + (size_t)NN * SD;   // final h lives in d_out directly

    // --- launches 0..4: minimal prerequisites for the layer-0 AB GEMM ---
    {
        const float* W1a = W1;
        const float* W1b = W1 + KK;
        convW_kernel<<<cg, cb>>>(W1a, W1b, p_WtAB, HID);                        // 0
        convW_kernel<<<cg, cb>>>(W1b, nullptr, p_WtAB + (size_t)1024 * K3, HID);// 1
        proj_kernel<<<(NN * HID + 255) / 256, 256>>>(x, proj_w, p_Abig);        // 2
        convW_kernel<<<cg, cb>>>(W2, nullptr, p_WtW2, HID);                     // 3
        zero_int_kernel<<<(NN + 255) / 256, 256>>>(p_deg, NN);                  // 4
    }
    // --- launch 5: the dominant kernel (ncu target) ---
    mma_gemm<0><<<gAB, 128, MM_SMEM>>>(p_Abig, p_WtAB, p_HAB, NN, 2048, nullptr, nullptr, nullptr);

    // --- CSR build + remaining weight conversions (stream-serial) ---
    hist_kernel<<<(EE + 255) / 256, 256>>>(e_dst, p_deg);
    scan_kernel<<<1, 1024>>>(p_deg, p_off);
    copy_off_kernel<<<(NN + 255) / 256, 256>>>(p_off, p_cur);
    scatter_kernel<<<(EE + 255) / 256, 256>>>(e_src, e_dst, p_cur, p_srcs);
    sort_kernel<<<(NN + 255) / 256, 256>>>(p_off, p_srcs);
    for (int l = 1; l < LAYERS; l++) {
        const float* W1a = W1 + (size_t)l * 2 * KK;
        const float* W1b = W1a + KK;
        __nv_bfloat16* WtAB = p_WtAB + (size_t)l * 2048 * K3;
        convW_kernel<<<cg, cb>>>(W1a, W1b, WtAB, HID);
        convW_kernel<<<cg, cb>>>(W1b, nullptr, WtAB + (size_t)1024 * K3, HID);
        convW_kernel<<<cg, cb>>>(W2 + (size_t)l * KK, nullptr, p_WtW2 + (size_t)l * HID * K3, HID);
    }
    convW_kernel<<<cgh, cb>>>(gw1, nullptr, p_WtG, 256);

    // --- layers (layer 0's AB GEMM already issued above) ---
    for (int l = 0; l < LAYERS; l++) {
        const __nv_bfloat16* WtAB = p_WtAB + (size_t)l * 2048 * K3;
        const __nv_bfloat16* WtW2 = p_WtW2 + (size_t)l * HID * K3;
        const float* b1l = b1 + (size_t)l * HID;
        const float* b2l = b2 + (size_t)l * HID;
        float* hout = (l == LAYERS - 1) ? h_last : p_h;

        if (l > 0)
            mma_gemm<0><<<gAB, 128, MM_SMEM>>>(p_Abig, WtAB, p_HAB, NN, 2048, nullptr, nullptr, nullptr);
        edge_agg_kernel<<<NN, 256>>>(p_HAB, p_off, p_srcs, b1l, p_Rbig);
        mma_gemm<1><<<gW2, 128, MM_SMEM>>>(p_Rbig, WtW2, hout, NN, HID, b2l, p_deg, p_Abig);
    }

    // --- heads (final h already resides in d_out) ---
    mma_gemm<2><<<ghead, 128, MM_SMEM>>>(p_Abig, p_WtG, p_t, NN, 256, gb1, nullptr, nullptr);
    ghost_kernel<<<(NN * 32 + 255) / 256, 256>>>(p_t, gw2, gb2, out);
    stable_kernel<<<NN, dim3(32, SD)>>>(h_last, sw, sb, out + NN);
}

// round 9
// speedup vs baseline: 2.8794x; 1.0945x over previous
#include <cuda_runtime.h>
#include <cuda_bf16.h>
#include <math.h>
#include <stdint.h>

// Problem constants
#define NN   10000
#define EE   80000
#define SD   18
#define HID  1024
#define K3   3072          // split-K: [hi | lo | hi] x [whi | whi | wlo]
#define LAYERS 4

// GEMM tiling: BM=BN=128, BK=64, 128 threads (4 warps, 2x2 grid of 64x64 warp tiles)
// SW128 XOR swizzle, dense 128B rows, 3-stage cp.async pipeline.
#define BM 128
#define BN 128
#define BK 64
#define STG 3
#define NK (K3 / BK)               // 48
#define TILE_BYTES (128 * 128)     // 16384
#define STAGE_BYTES (2 * TILE_BYTES)
#define MM_SMEM (STG * STAGE_BYTES)   // 98304

// ---------------------------------------------------------------------------
// Scratch (device globals — no runtime allocation allowed)
// ---------------------------------------------------------------------------
__device__ float g_h  [NN * HID];
__device__ float g_HAB[NN * 2048];
__device__ float g_t  [NN * 256];
__device__ __nv_bfloat16 g_Abig[NN * K3];
__device__ __nv_bfloat16 g_Rbig[NN * K3];
__device__ __nv_bfloat16 g_WtAB[LAYERS * 2048 * K3];
__device__ __nv_bfloat16 g_WtW2[LAYERS * HID * K3];
__device__ __nv_bfloat16 g_WtG [256 * K3];
__device__ int   g_deg[NN];
__device__ int   g_off[NN + 1];
__device__ int   g_cur[NN];
__device__ int   g_srcs[EE];

// ---------------------------------------------------------------------------
// PTX helpers (baseline ISA only: cp.async / ldmatrix / mma.sync)
// ---------------------------------------------------------------------------
__device__ __forceinline__ uint32_t smem_u32(const void* p) {
    uint32_t a;
    asm("{ .reg .u64 t; cvta.to.shared.u64 t, %1; cvt.u32.u64 %0, t; }" : "=r"(a) : "l"(p));
    return a;
}
__device__ __forceinline__ void cp16(uint32_t dst, const void* src, bool valid) {
    int sz = valid ? 16 : 0;
    asm volatile("cp.async.cg.shared.global [%0], [%1], 16, %2;" :: "r"(dst), "l"(src), "r"(sz) : "memory");
}
__device__ __forceinline__ void cp_commit() { asm volatile("cp.async.commit_group;" ::: "memory"); }
__device__ __forceinline__ void ldm_x4(uint32_t& r0, uint32_t& r1, uint32_t& r2, uint32_t& r3,
                                       uint32_t addr) {
    asm volatile("ldmatrix.sync.aligned.m8n8.x4.shared.b16 {%0,%1,%2,%3}, [%4];"
                 : "=r"(r0), "=r"(r1), "=r"(r2), "=r"(r3) : "r"(addr));
}
__device__ __forceinline__ void mma_bf16(float& c0, float& c1, float& c2, float& c3,
                                         uint32_t a0, uint32_t a1, uint32_t a2, uint32_t a3,
                                         uint32_t b0, uint32_t b1) {
    asm volatile(
        "mma.sync.aligned.m16n8k16.row.col.f32.bf16.bf16.f32 "
        "{%0,%1,%2,%3}, {%4,%5,%6,%7}, {%8,%9}, {%0,%1,%2,%3};"
        : "+f"(c0), "+f"(c1), "+f"(c2), "+f"(c3)
        : "r"(a0), "r"(a1), "r"(a2), "r"(a3), "r"(b0), "r"(b1));
}

// ---------------------------------------------------------------------------
// HMMA GEMM: C[M, Nstride] = A[M, K3] @ Bt[N, K3]^T  (bf16 in, fp32 out)
// MODE 0: plain C
// MODE 1: v = relu(acc + deg[row]*bias[col]); writes C (fp32) AND abig split
// MODE 2: relu(acc + bias[col]) -> C
// MODE 3: v = relu(acc + deg[row]*bias[col]); writes abig split ONLY
// 128 threads, 4 warps in 2(M) x 2(N); warp tile 64x64; frag m16n8k16.
// Smem: dense 128B rows, 16B-chunk XOR swizzle (chunk' = chunk ^ (row&7)),
// conflict-free for both cp.async stores and ldmatrix reads.
// ---------------------------------------------------------------------------
template <int MODE>
__global__ void __launch_bounds__(128, 2)
mma_gemm(const __nv_bfloat16* __restrict__ A, const __nv_bfloat16* __restrict__ Bt,
         float* __restrict__ C, int M, int Nstride,
         const float* __restrict__ bias, const int* __restrict__ deg,
         __nv_bfloat16* __restrict__ abig) {
    extern __shared__ char smem[];
    const uint32_t sb = smem_u32(smem);
    const int tid  = threadIdx.x;
    const int wid  = tid >> 5;
    const int lane = tid & 31;
    const int bm   = blockIdx.y * BM;
    const int bn   = blockIdx.x * BN;
    const int warp_m = (wid & 1) * 64;
    const int warp_n = (wid >> 1) * 64;

    // cp.async mapping: per operand 1024 16B-chunks; thread t covers
    // rows (t>>3)+16u (u=0..7), chunk q = t&7  -> warp reads 4 rows x 128B contiguous.
    const char* gA = (const char*)A  + (size_t)bm * (K3 * 2);
    const char* gB = (const char*)Bt + (size_t)bn * (K3 * 2);
    const int lrow = tid >> 3;
    const int qq   = (tid & 7) * 16;

    auto load_chunk = [&](int kc, int s) {
        uint32_t sa = sb + s * STAGE_BYTES;
        uint32_t sB = sa + TILE_BYTES;
        size_t kb = (size_t)kc * (BK * 2);
#pragma unroll
        for (int u = 0; u < 8; u++) {
            int row = lrow + u * 16;
            uint32_t sw = row * 128 + (qq ^ ((row & 7) << 4));
            cp16(sa + sw, gA + (size_t)row * (K3 * 2) + kb + qq, (bm + row) < M);
            cp16(sB + sw, gB + (size_t)row * (K3 * 2) + kb + qq, true);
        }
        cp_commit();
    };

    // ldmatrix lane patterns (same logical mapping as padded version, swizzled)
    const int g  = lane >> 3;
    const int lr = lane & 7;
    const int swz = lr << 4;
    const int A_row = (g & 1) * 8 + lr;      // row within 16-row tile
    const int A_col = (g >> 1) * 16;         // byte col within k16 (0 or 16)
    const int B_row = (g >> 1) * 8 + lr;
    const int B_col = (g & 1) * 16;

    float acc[4][8][4];
#pragma unroll
    for (int i = 0; i < 4; i++)
#pragma unroll
        for (int j = 0; j < 8; j++)
#pragma unroll
            for (int q = 0; q < 4; q++) acc[i][j][q] = 0.f;

    // prologue
#pragma unroll
    for (int s = 0; s < STG - 1; s++) load_chunk(s, s);

    for (int it = 0; it < NK; it++) {
        asm volatile("cp.async.wait_group %0;" :: "n"(STG - 2) : "memory");
        __syncthreads();
        int cl = it + STG - 1;
        if (cl < NK) load_chunk(cl, cl % STG);
        else         cp_commit();      // empty group keeps wait_group bookkeeping valid

        uint32_t sa = sb + (it % STG) * STAGE_BYTES;
        uint32_t sB = sa + TILE_BYTES;
        uint32_t aBase = sa + (warp_m + A_row) * 128;
        uint32_t bBase = sB + (warp_n + B_row) * 128;
#pragma unroll
        for (int kk = 0; kk < 4; kk++) {
            uint32_t a[4][4], b[4][4];
            uint32_t aoff = (uint32_t)((kk * 32 + A_col) ^ swz);
            uint32_t boff = (uint32_t)((kk * 32 + B_col) ^ swz);
#pragma unroll
            for (int mt = 0; mt < 4; mt++)
                ldm_x4(a[mt][0], a[mt][1], a[mt][2], a[mt][3],
                       aBase + mt * (16 * 128) + aoff);
#pragma unroll
            for (int nt2 = 0; nt2 < 4; nt2++)
                ldm_x4(b[nt2][0], b[nt2][1], b[nt2][2], b[nt2][3],
                       bBase + nt2 * (16 * 128) + boff);
#pragma unroll
            for (int mt = 0; mt < 4; mt++)
#pragma unroll
                for (int nt = 0; nt < 8; nt++) {
                    uint32_t bb0 = b[nt >> 1][(nt & 1) * 2 + 0];
                    uint32_t bb1 = b[nt >> 1][(nt & 1) * 2 + 1];
                    mma_bf16(acc[mt][nt][0], acc[mt][nt][1], acc[mt][nt][2], acc[mt][nt][3],
                             a[mt][0], a[mt][1], a[mt][2], a[mt][3], bb0, bb1);
                }
        }
    }

    // epilogue (register-only inputs; no smem reads, no barrier needed)
    const int tq = lane >> 2;      // 0..7
    const int tr = lane & 3;       // 0..3
#pragma unroll
    for (int mt = 0; mt < 4; mt++) {
#pragma unroll
        for (int half = 0; half < 2; half++) {
            int row = bm + warp_m + mt * 16 + half * 8 + tq;
            if (row >= M) continue;
            float degf = 0.f;
            if (MODE == 1 || MODE == 3) degf = (float)deg[row];
#pragma unroll
            for (int nt = 0; nt < 8; nt++) {
                int col = bn + warp_n + nt * 8 + tr * 2;
                float vx = acc[mt][nt][half * 2 + 0];
                float vy = acc[mt][nt][half * 2 + 1];
                if (MODE == 1 || MODE == 3) {
                    vx = fmaxf(fmaf(degf, bias[col + 0], vx), 0.f);
                    vy = fmaxf(fmaf(degf, bias[col + 1], vy), 0.f);
                } else if (MODE == 2) {
                    vx = fmaxf(vx + bias[col + 0], 0.f);
                    vy = fmaxf(vy + bias[col + 1], 0.f);
                }
                if (MODE != 3)
                    *reinterpret_cast<float2*>(&C[(size_t)row * Nstride + col]) = make_float2(vx, vy);
                if (MODE == 1 || MODE == 3) {
                    __nv_bfloat162 hi2, lo2;
                    hi2.x = __float2bfloat16(vx);
                    hi2.y = __float2bfloat16(vy);
                    lo2.x = __float2bfloat16(vx - __bfloat162float(hi2.x));
                    lo2.y = __float2bfloat16(vy - __bfloat162float(hi2.y));
                    size_t base = (size_t)row * K3 + col;
                    *reinterpret_cast<__nv_bfloat162*>(&abig[base])            = hi2;
                    *reinterpret_cast<__nv_bfloat162*>(&abig[base + HID])      = lo2;
                    *reinterpret_cast<__nv_bfloat162*>(&abig[base + 2 * HID])  = hi2;
                }
            }
        }
    }
}

// ---------------------------------------------------------------------------
// Weight transpose + bf16 split: out[n][0:K]=hi, [K:2K]=hi, [2K:3K]=lo
// W is [K=1024, N] row-major (optionally Wa - Wb)
// ---------------------------------------------------------------------------
__global__ void convW_kernel(const float* __restrict__ Wa, const float* __restrict__ Wb,
                             __nv_bfloat16* __restrict__ out, int N) {
    __shared__ float t[32][33];
    int n0 = blockIdx.x * 32, k0 = blockIdx.y * 32;
    int tx = threadIdx.x, ty = threadIdx.y;
#pragma unroll
    for (int r = ty; r < 32; r += 8) {
        float v = Wa[(size_t)(k0 + r) * N + n0 + tx];
        if (Wb) v -= Wb[(size_t)(k0 + r) * N + n0 + tx];
        t[r][tx] = v;
    }
    __syncthreads();
#pragma unroll
    for (int r = ty; r < 32; r += 8) {
        int n = n0 + r, k = k0 + tx;
        float v = t[tx][r];
        __nv_bfloat16 hi = __float2bfloat16(v);
        __nv_bfloat16 lo = __float2bfloat16(v - __bfloat162float(hi));
        size_t base = (size_t)n * K3;
        out[base + k] = hi;
        out[base + HID + k] = hi;
        out[base + 2 * HID + k] = lo;
    }
}

// ---------------------------------------------------------------------------
// CSR build (deterministic)
// ---------------------------------------------------------------------------
__global__ void zero_int_kernel(int* p, int n) {
    int i = blockIdx.x * blockDim.x + threadIdx.x;
    if (i < n) p[i] = 0;
}
__global__ void hist_kernel(const int* __restrict__ dst, int* __restrict__ deg) {
    int e = blockIdx.x * blockDim.x + threadIdx.x;
    if (e < EE) atomicAdd(&deg[dst[e]], 1);
}
__global__ void scan_kernel(const int* __restrict__ deg, int* __restrict__ off) {
    __shared__ int sh[1024];
    __shared__ int carry;
    if (threadIdx.x == 0) { carry = 0; off[0] = 0; }
    __syncthreads();
    for (int start = 0; start < NN; start += 1024) {
        int i = start + threadIdx.x;
        int v = (i < NN) ? deg[i] : 0;
        sh[threadIdx.x] = v;
        __syncthreads();
        for (int d = 1; d < 1024; d <<= 1) {
            int t = (threadIdx.x >= d) ? sh[threadIdx.x - d] : 0;
            __syncthreads();
            sh[threadIdx.x] += t;
            __syncthreads();
        }
        if (i < NN) off[i + 1] = carry + sh[threadIdx.x];
        __syncthreads();
        if (threadIdx.x == 1023) carry += sh[1023];
        __syncthreads();
    }
}
__global__ void copy_off_kernel(const int* __restrict__ off, int* __restrict__ cur) {
    int i = blockIdx.x * blockDim.x + threadIdx.x;
    if (i < NN) cur[i] = off[i];
}
__global__ void scatter_kernel(const int* __restrict__ src, const int* __restrict__ dst,
                               int* __restrict__ cur, int* __restrict__ srcs) {
    int e = blockIdx.x * blockDim.x + threadIdx.x;
    if (e < EE) {
        int p = atomicAdd(&cur[dst[e]], 1);
        srcs[p] = src[e];
    }
}
__global__ void sort_kernel(const int* __restrict__ off, int* __restrict__ srcs) {
    int i = blockIdx.x * blockDim.x + threadIdx.x;
    if (i >= NN) return;
    int a = off[i], b = off[i + 1];
    for (int x = a + 1; x < b; x++) {
        int v = srcs[x];
        int y = x - 1;
        while (y >= a && srcs[y] > v) { srcs[y + 1] = srcs[y]; y--; }
        srcs[y + 1] = v;
    }
}

// ---------------------------------------------------------------------------
// Phase embedding: writes split-bf16 Abig directly
// ---------------------------------------------------------------------------
__global__ void proj_kernel(const float* __restrict__ x, const float* __restrict__ pw,
                            __nv_bfloat16* __restrict__ Abig) {
    int idx = blockIdx.x * blockDim.x + threadIdx.x;
    if (idx >= NN * HID) return;
    int n = idx >> 10, j = idx & (HID - 1);
    float p = 0.f;
#pragma unroll
    for (int k = 0; k < SD; k++) p = fmaf(x[n * SD + k], pw[k * HID + j], p);
    float v = sinf(p) * cosf(p);
    __nv_bfloat16 hi = __float2bfloat16(v);
    __nv_bfloat16 lo = __float2bfloat16(v - __bfloat162float(hi));
    size_t base = (size_t)n * K3;
    Abig[base + j] = hi;
    Abig[base + HID + j] = lo;
    Abig[base + 2 * HID + j] = hi;
}

// ---------------------------------------------------------------------------
// Edge aggregation: R[i] = sum relu(HA[i] + HB[src] + b1); writes split bf16
// HAB layout: row n holds [HA(n) | HB(n)] (2048 floats)
// ---------------------------------------------------------------------------
__global__ void edge_agg_kernel(const float* __restrict__ HAB,
                                const int* __restrict__ off, const int* __restrict__ srcs,
                                const float* __restrict__ b1, __nv_bfloat16* __restrict__ Rbig) {
    int i   = blockIdx.x;
    int tid = threadIdx.x;
    float ha[4], acc[4];
#pragma unroll
    for (int u = 0; u < 4; u++) {
        int j  = tid + u * 256;
        ha[u]  = HAB[(size_t)i * 2048 + j] + b1[j];
        acc[u] = 0.f;
    }
    int s0 = off[i], s1 = off[i + 1];
    for (int e = s0; e < s1; e++) {
        int s = srcs[e];
        const float* hb = HAB + (size_t)s * 2048 + 1024;
#pragma unroll
        for (int u = 0; u < 4; u++) acc[u] += fmaxf(ha[u] + hb[tid + u * 256], 0.f);
    }
    size_t base = (size_t)i * K3;
#pragma unroll
    for (int u = 0; u < 4; u++) {
        int j = tid + u * 256;
        float v = acc[u];
        __nv_bfloat16 hi = __float2bfloat16(v);
        __nv_bfloat16 lo = __float2bfloat16(v - __bfloat162float(hi));
        Rbig[base + j] = hi;
        Rbig[base + HID + j] = lo;
        Rbig[base + 2 * HID + j] = hi;
    }
}

// ---------------------------------------------------------------------------
// Heads
// ---------------------------------------------------------------------------
__global__ void ghost_kernel(const float* __restrict__ t, const float* __restrict__ gw2,
                             const float* __restrict__ gb2, float* __restrict__ out) {
    int warp = (blockIdx.x * blockDim.x + threadIdx.x) >> 5;
    int lane = threadIdx.x & 31;
    if (warp >= NN) return;
    float s = 0.f;
#pragma unroll
    for (int k = lane; k < 256; k += 32) s = fmaf(t[(size_t)warp * 256 + k], gw2[k], s);
#pragma unroll
    for (int o = 16; o; o >>= 1) s += __shfl_xor_sync(0xFFFFFFFFu, s, o);
    if (lane == 0) out[warp] = 1.f / (1.f + expf(-(s + gb2[0])));
}
__global__ void stable_kernel(const float* __restrict__ h, const float* __restrict__ sw,
                              const float* __restrict__ sb, float* __restrict__ out) {
    int n    = blockIdx.x;
    int c    = threadIdx.y;
    int lane = threadIdx.x;
    float s  = 0.f;
    for (int k = lane; k < HID; k += 32) s = fmaf(h[(size_t)n * HID + k], sw[k * SD + c], s);
#pragma unroll
    for (int o = 16; o; o >>= 1) s += __shfl_xor_sync(0xFFFFFFFFu, s, o);
    if (lane == 0) out[(size_t)n * SD + c] = s + sb[c];
}

// ---------------------------------------------------------------------------
// Launch
// ---------------------------------------------------------------------------
extern "C" void kernel_launch(void* const* d_in, const int* in_sizes, int n_in,
                              void* d_out, int out_size) {
    const float* x      = (const float*)d_in[0];
    const int*   eidx   = (const int*)  d_in[1];
    const float* proj_w = (const float*)d_in[2];
    const float* W1     = (const float*)d_in[3];
    const float* b1     = (const float*)d_in[4];
    const float* W2     = (const float*)d_in[5];
    const float* b2     = (const float*)d_in[6];
    const float* gw1    = (const float*)d_in[7];
    const float* gb1    = (const float*)d_in[8];
    const float* gw2    = (const float*)d_in[9];
    const float* gb2    = (const float*)d_in[10];
    const float* sw     = (const float*)d_in[11];
    const float* sb     = (const float*)d_in[12];
    float* out = (float*)d_out;

    const int* e_src = eidx;
    const int* e_dst = eidx + EE;

    float *p_h, *p_HAB, *p_t;
    __nv_bfloat16 *p_Abig, *p_Rbig, *p_WtAB, *p_WtW2, *p_WtG;
    int *p_deg, *p_off, *p_cur, *p_srcs;
    cudaGetSymbolAddress((void**)&p_h,    g_h);
    cudaGetSymbolAddress((void**)&p_HAB,  g_HAB);
    cudaGetSymbolAddress((void**)&p_t,    g_t);
    cudaGetSymbolAddress((void**)&p_Abig, g_Abig);
    cudaGetSymbolAddress((void**)&p_Rbig, g_Rbig);
    cudaGetSymbolAddress((void**)&p_WtAB, g_WtAB);
    cudaGetSymbolAddress((void**)&p_WtW2, g_WtW2);
    cudaGetSymbolAddress((void**)&p_WtG,  g_WtG);
    cudaGetSymbolAddress((void**)&p_deg,  g_deg);
    cudaGetSymbolAddress((void**)&p_off,  g_off);
    cudaGetSymbolAddress((void**)&p_cur,  g_cur);
    cudaGetSymbolAddress((void**)&p_srcs, g_srcs);

    cudaFuncSetAttribute(mma_gemm<0>, cudaFuncAttributeMaxDynamicSharedMemorySize, MM_SMEM);
    cudaFuncSetAttribute(mma_gemm<1>, cudaFuncAttributeMaxDynamicSharedMemorySize, MM_SMEM);
    cudaFuncSetAttribute(mma_gemm<2>, cudaFuncAttributeMaxDynamicSharedMemorySize, MM_SMEM);
    cudaFuncSetAttribute(mma_gemm<3>, cudaFuncAttributeMaxDynamicSharedMemorySize, MM_SMEM);

    const size_t KK = (size_t)HID * HID;
    dim3 cb(32, 8);
    dim3 cg(HID / 32, HID / 32);
    dim3 cgh(256 / 32, HID / 32);
    const int NBM = (NN + BM - 1) / BM;      // 79
    dim3 gAB(2048 / BN, NBM);                // (16, 79)
    dim3 gW2(HID / BN, NBM);                 // (8, 79)
    dim3 ghead(256 / BN, NBM);               // (2, 79)
    float* h_last = out + NN + (size_t)NN * SD;   // final h lives in d_out directly

    // Weight conversions
    for (int l = 0; l < LAYERS; l++) {
        const float* W1a = W1 + (size_t)l * 2 * KK;
        const float* W1b = W1a + KK;
        __nv_bfloat16* WtAB = p_WtAB + (size_t)l * 2048 * K3;
        convW_kernel<<<cg, cb>>>(W1a, W1b, WtAB, HID);                         // rows 0..1023: A = W1a - W1b
        convW_kernel<<<cg, cb>>>(W1b, nullptr, WtAB + (size_t)1024 * K3, HID); // rows 1024..2047: B
        convW_kernel<<<cg, cb>>>(W2 + (size_t)l * KK, nullptr, p_WtW2 + (size_t)l * HID * K3, HID);
    }
    convW_kernel<<<cgh, cb>>>(gw1, nullptr, p_WtG, 256);

    // CSR build
    zero_int_kernel<<<(NN + 255) / 256, 256>>>(p_deg, NN);
    hist_kernel<<<(EE + 255) / 256, 256>>>(e_dst, p_deg);
    scan_kernel<<<1, 1024>>>(p_deg, p_off);
    copy_off_kernel<<<(NN + 255) / 256, 256>>>(p_off, p_cur);
    scatter_kernel<<<(EE + 255) / 256, 256>>>(e_src, e_dst, p_cur, p_srcs);
    sort_kernel<<<(NN + 255) / 256, 256>>>(p_off, p_srcs);

    // Phase embedding -> Abig (split bf16)
    proj_kernel<<<(NN * HID + 255) / 256, 256>>>(x, proj_w, p_Abig);

    // Layers: layers 0..2 skip the dead fp32 h store (MODE 3)
    for (int l = 0; l < LAYERS; l++) {
        const __nv_bfloat16* WtAB = p_WtAB + (size_t)l * 2048 * K3;
        const __nv_bfloat16* WtW2 = p_WtW2 + (size_t)l * HID * K3;
        const float* b1l = b1 + (size_t)l * HID;
        const float* b2l = b2 + (size_t)l * HID;

        mma_gemm<0><<<gAB, 128, MM_SMEM>>>(p_Abig, WtAB, p_HAB, NN, 2048, nullptr, nullptr, nullptr);
        edge_agg_kernel<<<NN, 256>>>(p_HAB, p_off, p_srcs, b1l, p_Rbig);
        if (l == LAYERS - 1)
            mma_gemm<1><<<gW2, 128, MM_SMEM>>>(p_Rbig, WtW2, h_last, NN, HID, b2l, p_deg, p_Abig);
        else
            mma_gemm<3><<<gW2, 128, MM_SMEM>>>(p_Rbig, WtW2, p_h, NN, HID, b2l, p_deg, p_Abig);
    }

    // Heads (final h already resides in d_out)
    mma_gemm<2><<<ghead, 128, MM_SMEM>>>(p_Abig, p_WtG, p_t, NN, 256, gb1, nullptr, nullptr);
    ghost_kernel<<<(NN * 32 + 255) / 256, 256>>>(p_t, gw2, gb2, out);
    stable_kernel<<<NN, dim3(32, SD)>>>(h_last, sw, sb, out + NN);
}

// round 10
// speedup vs baseline: 4.0136x; 1.3939x over previous
#include <cuda_runtime.h>
#include <cuda_fp16.h>
#include <math.h>
#include <stdint.h>

// Problem constants
#define NN   10000
#define EE   80000
#define SD   18
#define HID  1024
#define K2   2048          // fp16 2-term split: A=[hi|lo], W=[whi|whi]
#define LAYERS 4

// GEMM tiling: BM=BN=128, BK=64, 128 threads (4 warps, 2x2 grid of 64x64 warp tiles)
// SW128 XOR swizzle, dense 128B rows, 3-stage cp.async pipeline.
#define BM 128
#define BN 128
#define BK 64
#define STG 3
#define NK (K2 / BK)               // 32
#define TILE_BYTES (128 * 128)     // 16384
#define STAGE_BYTES (2 * TILE_BYTES)
#define MM_SMEM (STG * STAGE_BYTES)   // 98304

// ---------------------------------------------------------------------------
// Scratch (device globals — no runtime allocation allowed)
// ---------------------------------------------------------------------------
__device__ float g_h  [NN * HID];
__device__ float g_HAB[NN * 2048];
__device__ float g_t  [NN * 256];
__device__ __half g_Abig[NN * K2];
__device__ __half g_Rbig[NN * K2];
__device__ __half g_WtAB[LAYERS * 2048 * K2];
__device__ __half g_WtW2[LAYERS * HID * K2];
__device__ __half g_WtG [256 * K2];
__device__ int   g_deg[NN];
__device__ int   g_off[NN + 1];
__device__ int   g_cur[NN];
__device__ int   g_srcs[EE];

// ---------------------------------------------------------------------------
// PTX helpers (baseline ISA only: cp.async / ldmatrix / mma.sync)
// ---------------------------------------------------------------------------
__device__ __forceinline__ uint32_t smem_u32(const void* p) {
    uint32_t a;
    asm("{ .reg .u64 t; cvta.to.shared.u64 t, %1; cvt.u32.u64 %0, t; }" : "=r"(a) : "l"(p));
    return a;
}
__device__ __forceinline__ void cp16(uint32_t dst, const void* src, bool valid) {
    int sz = valid ? 16 : 0;
    asm volatile("cp.async.cg.shared.global [%0], [%1], 16, %2;" :: "r"(dst), "l"(src), "r"(sz) : "memory");
}
__device__ __forceinline__ void cp_commit() { asm volatile("cp.async.commit_group;" ::: "memory"); }
__device__ __forceinline__ void ldm_x4(uint32_t& r0, uint32_t& r1, uint32_t& r2, uint32_t& r3,
                                       uint32_t addr) {
    asm volatile("ldmatrix.sync.aligned.m8n8.x4.shared.b16 {%0,%1,%2,%3}, [%4];"
                 : "=r"(r0), "=r"(r1), "=r"(r2), "=r"(r3) : "r"(addr));
}
__device__ __forceinline__ void mma_fp16(float& c0, float& c1, float& c2, float& c3,
                                         uint32_t a0, uint32_t a1, uint32_t a2, uint32_t a3,
                                         uint32_t b0, uint32_t b1) {
    asm volatile(
        "mma.sync.aligned.m16n8k16.row.col.f32.f16.f16.f32 "
        "{%0,%1,%2,%3}, {%4,%5,%6,%7}, {%8,%9}, {%0,%1,%2,%3};"
        : "+f"(c0), "+f"(c1), "+f"(c2), "+f"(c3)
        : "r"(a0), "r"(a1), "r"(a2), "r"(a3), "r"(b0), "r"(b1));
}

// ---------------------------------------------------------------------------
// HMMA GEMM: C[M, Nstride] = A[M, K2] @ Bt[N, K2]^T  (fp16 in, fp32 out)
// MODE 0: plain C
// MODE 1: v = relu(acc + deg[row]*bias[col]); writes C (fp32) AND abig split
// MODE 2: relu(acc + bias[col]) -> C
// MODE 3: v = relu(acc + deg[row]*bias[col]); writes abig split ONLY
// 128 threads, 4 warps in 2(M) x 2(N); warp tile 64x64; frag m16n8k16.
// Smem: dense 128B rows, 16B-chunk XOR swizzle (chunk' = chunk ^ (row&7)),
// conflict-free for both cp.async stores and ldmatrix reads.
// ---------------------------------------------------------------------------
template <int MODE>
__global__ void __launch_bounds__(128, 2)
mma_gemm(const __half* __restrict__ A, const __half* __restrict__ Bt,
         float* __restrict__ C, int M, int Nstride,
         const float* __restrict__ bias, const int* __restrict__ deg,
         __half* __restrict__ abig) {
    extern __shared__ char smem[];
    const uint32_t sb = smem_u32(smem);
    const int tid  = threadIdx.x;
    const int wid  = tid >> 5;
    const int lane = tid & 31;
    const int bm   = blockIdx.y * BM;
    const int bn   = blockIdx.x * BN;
    const int warp_m = (wid & 1) * 64;
    const int warp_n = (wid >> 1) * 64;

    const char* gA = (const char*)A  + (size_t)bm * (K2 * 2);
    const char* gB = (const char*)Bt + (size_t)bn * (K2 * 2);
    const int lrow = tid >> 3;
    const int qq   = (tid & 7) * 16;

    auto load_chunk = [&](int kc, int s) {
        uint32_t sa = sb + s * STAGE_BYTES;
        uint32_t sB = sa + TILE_BYTES;
        size_t kb = (size_t)kc * (BK * 2);
#pragma unroll
        for (int u = 0; u < 8; u++) {
            int row = lrow + u * 16;
            uint32_t sw = row * 128 + (qq ^ ((row & 7) << 4));
            cp16(sa + sw, gA + (size_t)row * (K2 * 2) + kb + qq, (bm + row) < M);
            cp16(sB + sw, gB + (size_t)row * (K2 * 2) + kb + qq, true);
        }
        cp_commit();
    };

    // ldmatrix lane patterns
    const int g  = lane >> 3;
    const int lr = lane & 7;
    const int swz = lr << 4;
    const int A_row = (g & 1) * 8 + lr;
    const int A_col = (g >> 1) * 16;
    const int B_row = (g >> 1) * 8 + lr;
    const int B_col = (g & 1) * 16;

    float acc[4][8][4];
#pragma unroll
    for (int i = 0; i < 4; i++)
#pragma unroll
        for (int j = 0; j < 8; j++)
#pragma unroll
            for (int q = 0; q < 4; q++) acc[i][j][q] = 0.f;

    // prologue
#pragma unroll
    for (int s = 0; s < STG - 1; s++) load_chunk(s, s);

    for (int it = 0; it < NK; it++) {
        asm volatile("cp.async.wait_group %0;" :: "n"(STG - 2) : "memory");
        __syncthreads();
        int cl = it + STG - 1;
        if (cl < NK) load_chunk(cl, cl % STG);
        else         cp_commit();      // empty group keeps wait_group bookkeeping valid

        uint32_t sa = sb + (it % STG) * STAGE_BYTES;
        uint32_t sB = sa + TILE_BYTES;
        uint32_t aBase = sa + (warp_m + A_row) * 128;
        uint32_t bBase = sB + (warp_n + B_row) * 128;
#pragma unroll
        for (int kk = 0; kk < 4; kk++) {
            uint32_t a[4][4], b[4][4];
            uint32_t aoff = (uint32_t)((kk * 32 + A_col) ^ swz);
            uint32_t boff = (uint32_t)((kk * 32 + B_col) ^ swz);
#pragma unroll
            for (int mt = 0; mt < 4; mt++)
                ldm_x4(a[mt][0], a[mt][1], a[mt][2], a[mt][3],
                       aBase + mt * (16 * 128) + aoff);
#pragma unroll
            for (int nt2 = 0; nt2 < 4; nt2++)
                ldm_x4(b[nt2][0], b[nt2][1], b[nt2][2], b[nt2][3],
                       bBase + nt2 * (16 * 128) + boff);
#pragma unroll
            for (int mt = 0; mt < 4; mt++)
#pragma unroll
                for (int nt = 0; nt < 8; nt++) {
                    uint32_t bb0 = b[nt >> 1][(nt & 1) * 2 + 0];
                    uint32_t bb1 = b[nt >> 1][(nt & 1) * 2 + 1];
                    mma_fp16(acc[mt][nt][0], acc[mt][nt][1], acc[mt][nt][2], acc[mt][nt][3],
                             a[mt][0], a[mt][1], a[mt][2], a[mt][3], bb0, bb1);
                }
        }
    }

    // epilogue (register-only inputs; no smem reads, no barrier needed)
    const int tq = lane >> 2;      // 0..7
    const int tr = lane & 3;       // 0..3
#pragma unroll
    for (int mt = 0; mt < 4; mt++) {
#pragma unroll
        for (int half = 0; half < 2; half++) {
            int row = bm + warp_m + mt * 16 + half * 8 + tq;
            if (row >= M) continue;
            float degf = 0.f;
            if (MODE == 1 || MODE == 3) degf = (float)deg[row];
#pragma unroll
            for (int nt = 0; nt < 8; nt++) {
                int col = bn + warp_n + nt * 8 + tr * 2;
                float vx = acc[mt][nt][half * 2 + 0];
                float vy = acc[mt][nt][half * 2 + 1];
                if (MODE == 1 || MODE == 3) {
                    vx = fmaxf(fmaf(degf, bias[col + 0], vx), 0.f);
                    vy = fmaxf(fmaf(degf, bias[col + 1], vy), 0.f);
                } else if (MODE == 2) {
                    vx = fmaxf(vx + bias[col + 0], 0.f);
                    vy = fmaxf(vy + bias[col + 1], 0.f);
                }
                if (MODE != 3)
                    *reinterpret_cast<float2*>(&C[(size_t)row * Nstride + col]) = make_float2(vx, vy);
                if (MODE == 1 || MODE == 3) {
                    __half hx = __float2half(vx);
                    __half hy = __float2half(vy);
                    __half lx = __float2half(vx - __half2float(hx));
                    __half ly = __float2half(vy - __half2float(hy));
                    size_t base = (size_t)row * K2 + col;
                    *reinterpret_cast<__half2*>(&abig[base])       = __halves2half2(hx, hy);
                    *reinterpret_cast<__half2*>(&abig[base + HID]) = __halves2half2(lx, ly);
                }
            }
        }
    }
}

// ---------------------------------------------------------------------------
// Weight transpose + fp16: out[n][0:K]=whi, [K:2K]=whi
// W is [K=1024, N] row-major (optionally Wa - Wb)
// ---------------------------------------------------------------------------
__global__ void convW_kernel(const float* __restrict__ Wa, const float* __restrict__ Wb,
                             __half* __restrict__ out, int N) {
    __shared__ float t[32][33];
    int n0 = blockIdx.x * 32, k0 = blockIdx.y * 32;
    int tx = threadIdx.x, ty = threadIdx.y;
#pragma unroll
    for (int r = ty; r < 32; r += 8) {
        float v = Wa[(size_t)(k0 + r) * N + n0 + tx];
        if (Wb) v -= Wb[(size_t)(k0 + r) * N + n0 + tx];
        t[r][tx] = v;
    }
    __syncthreads();
#pragma unroll
    for (int r = ty; r < 32; r += 8) {
        int n = n0 + r, k = k0 + tx;
        __half hi = __float2half(t[tx][r]);
        size_t base = (size_t)n * K2;
        out[base + k] = hi;
        out[base + HID + k] = hi;
    }
}

// ---------------------------------------------------------------------------
// CSR build (deterministic)
// ---------------------------------------------------------------------------
__global__ void zero_int_kernel(int* p, int n) {
    int i = blockIdx.x * blockDim.x + threadIdx.x;
    if (i < n) p[i] = 0;
}
__global__ void hist_kernel(const int* __restrict__ dst, int* __restrict__ deg) {
    int e = blockIdx.x * blockDim.x + threadIdx.x;
    if (e < EE) atomicAdd(&deg[dst[e]], 1);
}
__global__ void scan_kernel(const int* __restrict__ deg, int* __restrict__ off) {
    __shared__ int sh[1024];
    __shared__ int carry;
    if (threadIdx.x == 0) { carry = 0; off[0] = 0; }
    __syncthreads();
    for (int start = 0; start < NN; start += 1024) {
        int i = start + threadIdx.x;
        int v = (i < NN) ? deg[i] : 0;
        sh[threadIdx.x] = v;
        __syncthreads();
        for (int d = 1; d < 1024; d <<= 1) {
            int t = (threadIdx.x >= d) ? sh[threadIdx.x - d] : 0;
            __syncthreads();
            sh[threadIdx.x] += t;
            __syncthreads();
        }
        if (i < NN) off[i + 1] = carry + sh[threadIdx.x];
        __syncthreads();
        if (threadIdx.x == 1023) carry += sh[1023];
        __syncthreads();
    }
}
__global__ void copy_off_kernel(const int* __restrict__ off, int* __restrict__ cur) {
    int i = blockIdx.x * blockDim.x + threadIdx.x;
    if (i < NN) cur[i] = off[i];
}
__global__ void scatter_kernel(const int* __restrict__ src, const int* __restrict__ dst,
                               int* __restrict__ cur, int* __restrict__ srcs) {
    int e = blockIdx.x * blockDim.x + threadIdx.x;
    if (e < EE) {
        int p = atomicAdd(&cur[dst[e]], 1);
        srcs[p] = src[e];
    }
}
__global__ void sort_kernel(const int* __restrict__ off, int* __restrict__ srcs) {
    int i = blockIdx.x * blockDim.x + threadIdx.x;
    if (i >= NN) return;
    int a = off[i], b = off[i + 1];
    for (int x = a + 1; x < b; x++) {
        int v = srcs[x];
        int y = x - 1;
        while (y >= a && srcs[y] > v) { srcs[y + 1] = srcs[y]; y--; }
        srcs[y + 1] = v;
    }
}

// ---------------------------------------------------------------------------
// Phase embedding: writes fp16 split Abig directly
// ---------------------------------------------------------------------------
__global__ void proj_kernel(const float* __restrict__ x, const float* __restrict__ pw,
                            __half* __restrict__ Abig) {
    int idx = blockIdx.x * blockDim.x + threadIdx.x;
    if (idx >= NN * HID) return;
    int n = idx >> 10, j = idx & (HID - 1);
    float p = 0.f;
#pragma unroll
    for (int k = 0; k < SD; k++) p = fmaf(x[n * SD + k], pw[k * HID + j], p);
    float v = sinf(p) * cosf(p);
    __half hi = __float2half(v);
    __half lo = __float2half(v - __half2float(hi));
    size_t base = (size_t)n * K2;
    Abig[base + j] = hi;
    Abig[base + HID + j] = lo;
}

// ---------------------------------------------------------------------------
// Edge aggregation: R[i] = sum relu(HA[i] + HB[src] + b1); writes fp16 split
// HAB layout: row n holds [HA(n) | HB(n)] (2048 floats)
// ---------------------------------------------------------------------------
__global__ void edge_agg_kernel(const float* __restrict__ HAB,
                                const int* __restrict__ off, const int* __restrict__ srcs,
                                const float* __restrict__ b1, __half* __restrict__ Rbig) {
    int i   = blockIdx.x;
    int tid = threadIdx.x;
    float ha[4], acc[4];
#pragma unroll
    for (int u = 0; u < 4; u++) {
        int j  = tid + u * 256;
        ha[u]  = HAB[(size_t)i * 2048 + j] + b1[j];
        acc[u] = 0.f;
    }
    int s0 = off[i], s1 = off[i + 1];
    for (int e = s0; e < s1; e++) {
        int s = srcs[e];
        const float* hb = HAB + (size_t)s * 2048 + 1024;
#pragma unroll
        for (int u = 0; u < 4; u++) acc[u] += fmaxf(ha[u] + hb[tid + u * 256], 0.f);
    }
    size_t base = (size_t)i * K2;
#pragma unroll
    for (int u = 0; u < 4; u++) {
        int j = tid + u * 256;
        float v = acc[u];
        __half hi = __float2half(v);
        __half lo = __float2half(v - __half2float(hi));
        Rbig[base + j] = hi;
        Rbig[base + HID + j] = lo;
    }
}

// ---------------------------------------------------------------------------
// Heads
// ---------------------------------------------------------------------------
__global__ void ghost_kernel(const float* __restrict__ t, const float* __restrict__ gw2,
                             const float* __restrict__ gb2, float* __restrict__ out) {
    int warp = (blockIdx.x * blockDim.x + threadIdx.x) >> 5;
    int lane = threadIdx.x & 31;
    if (warp >= NN) return;
    float s = 0.f;
#pragma unroll
    for (int k = lane; k < 256; k += 32) s = fmaf(t[(size_t)warp * 256 + k], gw2[k], s);
#pragma unroll
    for (int o = 16; o; o >>= 1) s += __shfl_xor_sync(0xFFFFFFFFu, s, o);
    if (lane == 0) out[warp] = 1.f / (1.f + expf(-(s + gb2[0])));
}
__global__ void stable_kernel(const float* __restrict__ h, const float* __restrict__ sw,
                              const float* __restrict__ sb, float* __restrict__ out) {
    int n    = blockIdx.x;
    int c    = threadIdx.y;
    int lane = threadIdx.x;
    float s  = 0.f;
    for (int k = lane; k < HID; k += 32) s = fmaf(h[(size_t)n * HID + k], sw[k * SD + c], s);
#pragma unroll
    for (int o = 16; o; o >>= 1) s += __shfl_xor_sync(0xFFFFFFFFu, s, o);
    if (lane == 0) out[(size_t)n * SD + c] = s + sb[c];
}

// ---------------------------------------------------------------------------
// Launch
// ---------------------------------------------------------------------------
extern "C" void kernel_launch(void* const* d_in, const int* in_sizes, int n_in,
                              void* d_out, int out_size) {
    const float* x      = (const float*)d_in[0];
    const int*   eidx   = (const int*)  d_in[1];
    const float* proj_w = (const float*)d_in[2];
    const float* W1     = (const float*)d_in[3];
    const float* b1     = (const float*)d_in[4];
    const float* W2     = (const float*)d_in[5];
    const float* b2     = (const float*)d_in[6];
    const float* gw1    = (const float*)d_in[7];
    const float* gb1    = (const float*)d_in[8];
    const float* gw2    = (const float*)d_in[9];
    const float* gb2    = (const float*)d_in[10];
    const float* sw     = (const float*)d_in[11];
    const float* sb     = (const float*)d_in[12];
    float* out = (float*)d_out;

    const int* e_src = eidx;
    const int* e_dst = eidx + EE;

    float *p_h, *p_HAB, *p_t;
    __half *p_Abig, *p_Rbig, *p_WtAB, *p_WtW2, *p_WtG;
    int *p_deg, *p_off, *p_cur, *p_srcs;
    cudaGetSymbolAddress((void**)&p_h,    g_h);
    cudaGetSymbolAddress((void**)&p_HAB,  g_HAB);
    cudaGetSymbolAddress((void**)&p_t,    g_t);
    cudaGetSymbolAddress((void**)&p_Abig, g_Abig);
    cudaGetSymbolAddress((void**)&p_Rbig, g_Rbig);
    cudaGetSymbolAddress((void**)&p_WtAB, g_WtAB);
    cudaGetSymbolAddress((void**)&p_WtW2, g_WtW2);
    cudaGetSymbolAddress((void**)&p_WtG,  g_WtG);
    cudaGetSymbolAddress((void**)&p_deg,  g_deg);
    cudaGetSymbolAddress((void**)&p_off,  g_off);
    cudaGetSymbolAddress((void**)&p_cur,  g_cur);
    cudaGetSymbolAddress((void**)&p_srcs, g_srcs);

    cudaFuncSetAttribute(mma_gemm<0>, cudaFuncAttributeMaxDynamicSharedMemorySize, MM_SMEM);
    cudaFuncSetAttribute(mma_gemm<1>, cudaFuncAttributeMaxDynamicSharedMemorySize, MM_SMEM);
    cudaFuncSetAttribute(mma_gemm<2>, cudaFuncAttributeMaxDynamicSharedMemorySize, MM_SMEM);
    cudaFuncSetAttribute(mma_gemm<3>, cudaFuncAttributeMaxDynamicSharedMemorySize, MM_SMEM);

    const size_t KK = (size_t)HID * HID;
    dim3 cb(32, 8);
    dim3 cg(HID / 32, HID / 32);
    dim3 cgh(256 / 32, HID / 32);
    const int NBM = (NN + BM - 1) / BM;      // 79
    dim3 gAB(2048 / BN, NBM);                // (16, 79)
    dim3 gW2(HID / BN, NBM);                 // (8, 79)
    dim3 ghead(256 / BN, NBM);               // (2, 79)
    float* h_last = out + NN + (size_t)NN * SD;   // final h lives in d_out directly

    // Weight conversions
    for (int l = 0; l < LAYERS; l++) {
        const float* W1a = W1 + (size_t)l * 2 * KK;
        const float* W1b = W1a + KK;
        __half* WtAB = p_WtAB + (size_t)l * 2048 * K2;
        convW_kernel<<<cg, cb>>>(W1a, W1b, WtAB, HID);                         // rows 0..1023: A = W1a - W1b
        convW_kernel<<<cg, cb>>>(W1b, nullptr, WtAB + (size_t)1024 * K2, HID); // rows 1024..2047: B
        convW_kernel<<<cg, cb>>>(W2 + (size_t)l * KK, nullptr, p_WtW2 + (size_t)l * HID * K2, HID);
    }
    convW_kernel<<<cgh, cb>>>(gw1, nullptr, p_WtG, 256);

    // CSR build
    zero_int_kernel<<<(NN + 255) / 256, 256>>>(p_deg, NN);
    hist_kernel<<<(EE + 255) / 256, 256>>>(e_dst, p_deg);
    scan_kernel<<<1, 1024>>>(p_deg, p_off);
    copy_off_kernel<<<(NN + 255) / 256, 256>>>(p_off, p_cur);
    scatter_kernel<<<(EE + 255) / 256, 256>>>(e_src, e_dst, p_cur, p_srcs);
    sort_kernel<<<(NN + 255) / 256, 256>>>(p_off, p_srcs);

    // Phase embedding -> Abig (fp16 split)
    proj_kernel<<<(NN * HID + 255) / 256, 256>>>(x, proj_w, p_Abig);

    // Layers: layers 0..2 skip the dead fp32 h store (MODE 3)
    for (int l = 0; l < LAYERS; l++) {
        const __half* WtAB = p_WtAB + (size_t)l * 2048 * K2;
        const __half* WtW2 = p_WtW2 + (size_t)l * HID * K2;
        const float* b1l = b1 + (size_t)l * HID;
        const float* b2l = b2 + (size_t)l * HID;

        mma_gemm<0><<<gAB, 128, MM_SMEM>>>(p_Abig, WtAB, p_HAB, NN, 2048, nullptr, nullptr, nullptr);
        edge_agg_kernel<<<NN, 256>>>(p_HAB, p_off, p_srcs, b1l, p_Rbig);
        if (l == LAYERS - 1)
            mma_gemm<1><<<gW2, 128, MM_SMEM>>>(p_Rbig, WtW2, h_last, NN, HID, b2l, p_deg, p_Abig);
        else
            mma_gemm<3><<<gW2, 128, MM_SMEM>>>(p_Rbig, WtW2, p_h, NN, HID, b2l, p_deg, p_Abig);
    }

    // Heads (final h already resides in d_out)
    mma_gemm<2><<<ghead, 128, MM_SMEM>>>(p_Abig, p_WtG, p_t, NN, 256, gb1, nullptr, nullptr);
    ghost_kernel<<<(NN * 32 + 255) / 256, 256>>>(p_t, gw2, gb2, out);
    stable_kernel<<<NN, dim3(32, SD)>>>(h_last, sw, sb, out + NN);
}